// round 8
// baseline (speedup 1.0000x reference)
#include <cuda_runtime.h>
#include <cuda_fp16.h>
#include <cstdint>
#include <cstddef>

// ---------------------------------------------------------------------------
// CausalSelfAttention: out = proj( causal_attn( x @ Wqkv^T ) )
// fp16 mma.sync m16n8k16. GEMM: block 128x256, warp tile 64x64 (CUTLASS shape,
// smem-traffic-optimal). Attention: fp16 flash kernel.
// ---------------------------------------------------------------------------

#define BATCH   4
#define S_LEN   2048
#define D_MODEL 1024
#define D3      3072
#define N_HEADS 16
#define DH      64
#define M_ROWS  (BATCH * S_LEN)   // 8192

__device__ __half g_qkv[(size_t)M_ROWS * D3];
__device__ __half g_y[(size_t)M_ROWS * D_MODEL];
__device__ __half g_xc[(size_t)M_ROWS * D_MODEL];
__device__ __half g_wac[(size_t)D3 * D_MODEL];
__device__ __half g_wpc[(size_t)D_MODEL * D_MODEL];

// ---- helpers ----------------------------------------------------------------
__device__ __forceinline__ uint32_t pack_h2(float a, float b) {
    __half2 h = __floats2half2_rn(a, b);
    return *(uint32_t*)&h;
}
__device__ __forceinline__ float ex2f(float x) {
    float r;
    asm("ex2.approx.ftz.f32 %0, %1;" : "=f"(r) : "f"(x));
    return r;
}
__device__ __forceinline__ void ldsm_x4(uint32_t addr, uint32_t& r0, uint32_t& r1,
                                        uint32_t& r2, uint32_t& r3) {
    asm volatile("ldmatrix.sync.aligned.m8n8.x4.shared.b16 {%0,%1,%2,%3}, [%4];"
                 : "=r"(r0), "=r"(r1), "=r"(r2), "=r"(r3) : "r"(addr));
}
__device__ __forceinline__ void ldsm_x4t(uint32_t addr, uint32_t& r0, uint32_t& r1,
                                         uint32_t& r2, uint32_t& r3) {
    asm volatile("ldmatrix.sync.aligned.m8n8.x4.trans.shared.b16 {%0,%1,%2,%3}, [%4];"
                 : "=r"(r0), "=r"(r1), "=r"(r2), "=r"(r3) : "r"(addr));
}
__device__ __forceinline__ void mma_f16(float& c0, float& c1, float& c2, float& c3,
                                        uint32_t a0, uint32_t a1, uint32_t a2, uint32_t a3,
                                        uint32_t b0, uint32_t b1) {
    asm volatile("mma.sync.aligned.m16n8k16.row.col.f32.f16.f16.f32 "
                 "{%0,%1,%2,%3}, {%4,%5,%6,%7}, {%8,%9}, {%0,%1,%2,%3};"
                 : "+f"(c0), "+f"(c1), "+f"(c2), "+f"(c3)
                 : "r"(a0), "r"(a1), "r"(a2), "r"(a3), "r"(b0), "r"(b1));
}
__device__ __forceinline__ void cp16(uint32_t dst, const void* src) {
    asm volatile("cp.async.cg.shared.global [%0], [%1], 16;" :: "r"(dst), "l"(src));
}
#define CP_COMMIT() asm volatile("cp.async.commit_group;")
#define CP_WAIT(n)  asm volatile("cp.async.wait_group %0;" :: "n"(n))

__device__ __forceinline__ uint32_t smem_u32(const void* p) {
    return (uint32_t)__cvta_generic_to_shared(p);
}

// ---------------------------------------------------------------------------
// Pre-round fp32 -> fp16
// ---------------------------------------------------------------------------
__global__ void round_f16(const float* __restrict__ in, __half* __restrict__ out, int n4) {
    int i = blockIdx.x * blockDim.x + threadIdx.x;
    if (i < n4) {
        float4 v = ((const float4*)in)[i];
        uint2 r = {pack_h2(v.x, v.y), pack_h2(v.z, v.w)};
        ((uint2*)out)[i] = r;
    }
}

// ---------------------------------------------------------------------------
// fp16 GEMM (NT): C[M,N] = A[M,K] @ B[N,K]^T
// Block 128x256x(32 halfs); 8 warps in 2(m)x4(n); warp tile 64x64.
// 4-stage cp.async ring (A 8KB + B 16KB per stage = 96KB smem), 1 CTA/SM.
// ---------------------------------------------------------------------------
#define TBM 128
#define TBN 256
#define TBKH 32
#define GSTG 4
#define GA_BYTES 8192
#define GB_BYTES 16384
#define G_STAGE_BYTES (GA_BYTES + GB_BYTES)   // 24576
#define GEMM_SMEM (GSTG * G_STAGE_BYTES)      // 98304

template <bool HALF_OUT>
__global__ __launch_bounds__(256)
void gemm_f16(const __half* __restrict__ A, const __half* __restrict__ B,
              void* __restrict__ Cv, int M, int N, int K) {
    extern __shared__ uint32_t sh[];

    const int tid    = threadIdx.x;
    const int lane   = tid & 31;
    const int warp   = tid >> 5;
    const int warp_m = warp >> 2;      // 0..1
    const int warp_n = warp & 3;       // 0..3
    const int row0   = blockIdx.y * TBM;
    const int col0   = blockIdx.x * TBN;

    const __half* Ab = A + (size_t)row0 * K;
    const __half* Bb = B + (size_t)col0 * K;

    const uint32_t base = smem_u32(sh);
    uint32_t sA[GSTG], sB[GSTG];
#pragma unroll
    for (int s = 0; s < GSTG; s++) { sA[s] = base + s * G_STAGE_BYTES; sB[s] = sA[s] + GA_BYTES; }

    // cp.async mapping: A 128x4chunks=512 (2/thr), B 256x4=1024 (4/thr)
    const __half* a_src[2];
    uint32_t a_rel[2];
#pragma unroll
    for (int r = 0; r < 2; r++) {
        int idx = tid + 256 * r, row = idx >> 2, c = idx & 3;
        a_src[r] = Ab + (size_t)row * K + c * 8;
        a_rel[r] = (uint32_t)(row * 64 + ((c ^ ((row >> 1) & 3)) << 4));
    }
    const __half* b_src[4];
    uint32_t b_rel[4];
#pragma unroll
    for (int r = 0; r < 4; r++) {
        int idx = tid + 256 * r, row = idx >> 2, c = idx & 3;
        b_src[r] = Bb + (size_t)row * K + c * 8;
        b_rel[r] = (uint32_t)(row * 64 + ((c ^ ((row >> 1) & 3)) << 4));
    }

    // ldsm offsets within a stage
    uint32_t a_off[4][2], b_off[4][2];
    {
        int mat = lane >> 3, r = lane & 7;
#pragma unroll
        for (int mt = 0; mt < 4; mt++)
#pragma unroll
            for (int ks = 0; ks < 2; ks++) {
                int row = warp_m * 64 + mt * 16 + ((mat & 1) << 3) + r;
                int ch  = ks * 2 + (mat >> 1);
                a_off[mt][ks] = (uint32_t)(row * 64 + ((ch ^ ((row >> 1) & 3)) << 4));
            }
#pragma unroll
        for (int ntp = 0; ntp < 4; ntp++)
#pragma unroll
            for (int ks = 0; ks < 2; ks++) {
                int row = warp_n * 64 + ntp * 16 + ((mat >> 1) << 3) + r;
                int ch  = ks * 2 + (mat & 1);
                b_off[ntp][ks] = (uint32_t)(row * 64 + ((ch ^ ((row >> 1) & 3)) << 4));
            }
    }

    float c[4][8][4];
#pragma unroll
    for (int i = 0; i < 4; i++)
#pragma unroll
        for (int j = 0; j < 8; j++)
#pragma unroll
            for (int q = 0; q < 4; q++) c[i][j][q] = 0.f;

    const int NIT = K / TBKH;   // 32

    // prologue: stages 0..2
#pragma unroll
    for (int s = 0; s < 3; s++) {
#pragma unroll
        for (int r = 0; r < 2; r++) cp16(sA[s] + a_rel[r], a_src[r] + s * TBKH);
#pragma unroll
        for (int r = 0; r < 4; r++) cp16(sB[s] + b_rel[r], b_src[r] + s * TBKH);
        CP_COMMIT();
    }

    int buf = 0, nxt = 3;
    for (int it = 0; it < NIT; it++) {
        if (it + 3 < NIT) {
            const int k0 = (it + 3) * TBKH;
#pragma unroll
            for (int r = 0; r < 2; r++) cp16(sA[nxt] + a_rel[r], a_src[r] + k0);
#pragma unroll
            for (int r = 0; r < 4; r++) cp16(sB[nxt] + b_rel[r], b_src[r] + k0);
        }
        CP_COMMIT();
        CP_WAIT(3);
        __syncthreads();

#pragma unroll
        for (int ks = 0; ks < 2; ks++) {
            uint32_t af[4][4];
#pragma unroll
            for (int mt = 0; mt < 4; mt++)
                ldsm_x4(sA[buf] + a_off[mt][ks], af[mt][0], af[mt][1], af[mt][2], af[mt][3]);
            uint32_t bf[4][4];
#pragma unroll
            for (int ntp = 0; ntp < 4; ntp++)
                ldsm_x4(sB[buf] + b_off[ntp][ks], bf[ntp][0], bf[ntp][1], bf[ntp][2], bf[ntp][3]);
#pragma unroll
            for (int mt = 0; mt < 4; mt++)
#pragma unroll
                for (int nt = 0; nt < 8; nt++) {
                    const uint32_t* bp = &bf[nt >> 1][(nt & 1) * 2];
                    mma_f16(c[mt][nt][0], c[mt][nt][1], c[mt][nt][2], c[mt][nt][3],
                            af[mt][0], af[mt][1], af[mt][2], af[mt][3], bp[0], bp[1]);
                }
        }
        __syncthreads();
        buf = (buf + 1) & (GSTG - 1);
        nxt = (nxt + 1) & (GSTG - 1);
    }

    const int rql = lane >> 2;
    const int cpl = (lane & 3) * 2;
#pragma unroll
    for (int mt = 0; mt < 4; mt++) {
        int rg = row0 + warp_m * 64 + mt * 16 + rql;
#pragma unroll
        for (int nt = 0; nt < 8; nt++) {
            int cg = col0 + warp_n * 64 + nt * 8 + cpl;
            if (HALF_OUT) {
                __half* C = (__half*)Cv;
                *(uint32_t*)(C + (size_t)rg * N + cg)       = pack_h2(c[mt][nt][0], c[mt][nt][1]);
                *(uint32_t*)(C + (size_t)(rg + 8) * N + cg) = pack_h2(c[mt][nt][2], c[mt][nt][3]);
            } else {
                float* C = (float*)Cv;
                float2 v0 = {c[mt][nt][0], c[mt][nt][1]};
                float2 v1 = {c[mt][nt][2], c[mt][nt][3]};
                *(float2*)(C + (size_t)rg * N + cg)       = v0;
                *(float2*)(C + (size_t)(rg + 8) * N + cg) = v1;
            }
        }
    }
}

// ---------------------------------------------------------------------------
// fp16 causal flash attention (unchanged from R6/R7).
// ---------------------------------------------------------------------------
#define ATT_SCALE 0.18033688f
#define ATT_SMEM  49152

__global__ __launch_bounds__(256, 2)
void attn_f16(const __half* __restrict__ qkv, __half* __restrict__ y) {
    extern __shared__ uint32_t smu[];
    char* smc = (char*)smu;
    const uint32_t qs_base = smem_u32(smu);
    const uint32_t ks_base = qs_base + 16384;
    const uint32_t vs_base = ks_base + 16384;

    const int tid  = threadIdx.x;
    const int lane = tid & 31;
    const int w    = tid >> 5;
    const int qi   = (S_LEN / 128 - 1) - blockIdx.x;
    const int h    = blockIdx.y;
    const int b    = blockIdx.z;
    const int q0   = qi * 128;

    const __half* qb = qkv + (size_t)b * S_LEN * D3 + h * DH;
    const __half* kb = qb + D_MODEL;
    const __half* vb = qb + 2 * D_MODEL;

    int l_row[2], l_chk[2];
    uint32_t l_rel[2];
#pragma unroll
    for (int r = 0; r < 2; r++) {
        int idx = tid + 256 * r;
        l_row[r] = idx >> 3; l_chk[r] = idx & 7;
        l_rel[r] = (uint32_t)(l_row[r] * 128 + ((l_chk[r] ^ (l_row[r] & 7)) << 4));
    }

#pragma unroll
    for (int r = 0; r < 2; r++) {
        cp16(ks_base + l_rel[r], kb + (size_t)l_row[r] * D3 + l_chk[r] * 8);
        cp16(vs_base + l_rel[r], vb + (size_t)l_row[r] * D3 + l_chk[r] * 8);
    }
    CP_COMMIT();

#pragma unroll
    for (int r = 0; r < 4; r++) {
        int idx = tid + 256 * r, row = idx >> 3, ch = idx & 7;
        uint4 raw = *(const uint4*)(qb + (size_t)(q0 + row) * D3 + ch * 8);
        uint32_t* rp = (uint32_t*)&raw;
        uint4 outv;
        uint32_t* op = (uint32_t*)&outv;
#pragma unroll
        for (int j = 0; j < 4; j++) {
            __half2 hv = *(__half2*)&rp[j];
            float2 f = __half22float2(hv);
            op[j] = pack_h2(f.x * ATT_SCALE, f.y * ATT_SCALE);
        }
        *(uint4*)(smc + row * 128 + ((ch ^ (row & 7)) << 4)) = outv;
    }
    CP_WAIT(0);
    __syncthreads();

    const int mat = lane >> 3, rr = lane & 7;
    uint32_t qf[4][4];
    {
        int rowA = w * 16 + ((mat & 1) << 3) + rr;
        int rbase = rowA * 128;
        int rx = rowA & 7;
#pragma unroll
        for (int ks = 0; ks < 4; ks++) {
            int ch = ks * 2 + (mat >> 1);
            ldsm_x4(qs_base + rbase + ((ch ^ rx) << 4), qf[ks][0], qf[ks][1], qf[ks][2], qf[ks][3]);
        }
    }
    uint32_t krowOff[4]; int krx[4];
#pragma unroll
    for (int ntp = 0; ntp < 4; ntp++) {
        int rowB = ntp * 16 + ((mat >> 1) << 3) + rr;
        krowOff[ntp] = (uint32_t)(rowB * 128);
        krx[ntp] = rowB & 7;
    }
    const int kbit = mat & 1;
    uint32_t vrowOff[4]; int vrx[4];
#pragma unroll
    for (int kt = 0; kt < 4; kt++) {
        int rowV = kt * 16 + ((mat & 1) << 3) + rr;
        vrowOff[kt] = (uint32_t)(rowV * 128);
        vrx[kt] = rowV & 7;
    }
    const int vbit = mat >> 1;

    float m_lo = -1e30f, m_hi = -1e30f, l_lo = 0.f, l_hi = 0.f;
    float co[8][4];
#pragma unroll
    for (int i = 0; i < 8; i++)
#pragma unroll
        for (int q = 0; q < 4; q++) co[i][q] = 0.f;

    const int rlo  = q0 + w * 16 + (lane >> 2);
    const int jsel = lane & 3;

    const int njb = 2 * qi + 2;
    int buf = 0;

    for (int jb = 0; jb < njb; jb++) {
        if (jb + 1 < njb) {
            const int kn = (jb + 1) * 64;
            const uint32_t kd = ks_base + (buf ^ 1) * 8192;
            const uint32_t vd = vs_base + (buf ^ 1) * 8192;
#pragma unroll
            for (int r = 0; r < 2; r++) {
                cp16(kd + l_rel[r], kb + (size_t)(kn + l_row[r]) * D3 + l_chk[r] * 8);
                cp16(vd + l_rel[r], vb + (size_t)(kn + l_row[r]) * D3 + l_chk[r] * 8);
            }
        }
        CP_COMMIT();

        const uint32_t kbuf = ks_base + (uint32_t)(buf * 8192);
        const uint32_t vbuf = vs_base + (uint32_t)(buf * 8192);

        float cs[8][4];
#pragma unroll
        for (int i = 0; i < 8; i++)
#pragma unroll
            for (int q = 0; q < 4; q++) cs[i][q] = 0.f;

#pragma unroll
        for (int ks = 0; ks < 4; ks++) {
            uint32_t bf[4][4];
            int ch = ks * 2 + kbit;
#pragma unroll
            for (int ntp = 0; ntp < 4; ntp++)
                ldsm_x4(kbuf + krowOff[ntp] + ((ch ^ krx[ntp]) << 4),
                        bf[ntp][0], bf[ntp][1], bf[ntp][2], bf[ntp][3]);
#pragma unroll
            for (int nt = 0; nt < 8; nt++) {
                const uint32_t* bp = &bf[nt >> 1][(nt & 1) * 2];
                mma_f16(cs[nt][0], cs[nt][1], cs[nt][2], cs[nt][3],
                        qf[ks][0], qf[ks][1], qf[ks][2], qf[ks][3], bp[0], bp[1]);
            }
        }

        if (jb * 64 >= q0) {
#pragma unroll
            for (int nt = 0; nt < 8; nt++) {
                int cb = jb * 64 + nt * 8 + 2 * jsel;
                if (cb     > rlo)     cs[nt][0] = -1e30f;
                if (cb + 1 > rlo)     cs[nt][1] = -1e30f;
                if (cb     > rlo + 8) cs[nt][2] = -1e30f;
                if (cb + 1 > rlo + 8) cs[nt][3] = -1e30f;
            }
        }

        float ml = -1e30f, mh = -1e30f;
#pragma unroll
        for (int nt = 0; nt < 8; nt++) {
            ml = fmaxf(ml, fmaxf(cs[nt][0], cs[nt][1]));
            mh = fmaxf(mh, fmaxf(cs[nt][2], cs[nt][3]));
        }
        ml = fmaxf(ml, __shfl_xor_sync(0xffffffffu, ml, 1));
        ml = fmaxf(ml, __shfl_xor_sync(0xffffffffu, ml, 2));
        mh = fmaxf(mh, __shfl_xor_sync(0xffffffffu, mh, 1));
        mh = fmaxf(mh, __shfl_xor_sync(0xffffffffu, mh, 2));
        float Ml = fmaxf(m_lo, ml), Mh = fmaxf(m_hi, mh);
        float al = ex2f(m_lo - Ml), ah = ex2f(m_hi - Mh);
        m_lo = Ml; m_hi = Mh;

        float sl = 0.f, sh2 = 0.f;
#pragma unroll
        for (int nt = 0; nt < 8; nt++) {
            cs[nt][0] = ex2f(cs[nt][0] - Ml);
            cs[nt][1] = ex2f(cs[nt][1] - Ml);
            cs[nt][2] = ex2f(cs[nt][2] - Mh);
            cs[nt][3] = ex2f(cs[nt][3] - Mh);
            sl  += cs[nt][0] + cs[nt][1];
            sh2 += cs[nt][2] + cs[nt][3];
        }
        sl  += __shfl_xor_sync(0xffffffffu, sl, 1);
        sl  += __shfl_xor_sync(0xffffffffu, sl, 2);
        sh2 += __shfl_xor_sync(0xffffffffu, sh2, 1);
        sh2 += __shfl_xor_sync(0xffffffffu, sh2, 2);
        l_lo = l_lo * al + sl;
        l_hi = l_hi * ah + sh2;
#pragma unroll
        for (int i = 0; i < 8; i++) {
            co[i][0] *= al; co[i][1] *= al; co[i][2] *= ah; co[i][3] *= ah;
        }

#pragma unroll
        for (int kt = 0; kt < 4; kt++) {
            uint32_t pa0 = pack_h2(cs[2 * kt][0],     cs[2 * kt][1]);
            uint32_t pa1 = pack_h2(cs[2 * kt][2],     cs[2 * kt][3]);
            uint32_t pa2 = pack_h2(cs[2 * kt + 1][0], cs[2 * kt + 1][1]);
            uint32_t pa3 = pack_h2(cs[2 * kt + 1][2], cs[2 * kt + 1][3]);

#pragma unroll
            for (int ntp = 0; ntp < 4; ntp++) {
                uint32_t bf0, bf1, bf2, bf3;
                int ch = ntp * 2 + vbit;
                ldsm_x4t(vbuf + vrowOff[kt] + ((ch ^ vrx[kt]) << 4), bf0, bf1, bf2, bf3);
                mma_f16(co[2 * ntp][0], co[2 * ntp][1], co[2 * ntp][2], co[2 * ntp][3],
                        pa0, pa1, pa2, pa3, bf0, bf1);
                mma_f16(co[2 * ntp + 1][0], co[2 * ntp + 1][1], co[2 * ntp + 1][2], co[2 * ntp + 1][3],
                        pa0, pa1, pa2, pa3, bf2, bf3);
            }
        }

        CP_WAIT(0);
        __syncthreads();
        buf ^= 1;
    }

    const float il = 1.0f / l_lo, ih = 1.0f / l_hi;
    __half* yb = y + ((size_t)b * S_LEN + q0 + w * 16 + (lane >> 2)) * D_MODEL + h * DH + 2 * jsel;
#pragma unroll
    for (int nt = 0; nt < 8; nt++) {
        *(uint32_t*)(yb + nt * 8)                       = pack_h2(co[nt][0] * il, co[nt][1] * il);
        *(uint32_t*)(yb + nt * 8 + 8 * (size_t)D_MODEL) = pack_h2(co[nt][2] * ih, co[nt][3] * ih);
    }
}

// ---------------------------------------------------------------------------
extern "C" void kernel_launch(void* const* d_in, const int* in_sizes, int n_in,
                              void* d_out, int out_size) {
    const float* x      = (const float*)d_in[0];
    const float* w_attn = (const float*)d_in[1];
    const float* w_proj = (const float*)d_in[2];
    float* out = (float*)d_out;

    __half *qkv, *yb, *xc, *wac, *wpc;
    cudaGetSymbolAddress((void**)&qkv, g_qkv);
    cudaGetSymbolAddress((void**)&yb, g_y);
    cudaGetSymbolAddress((void**)&xc, g_xc);
    cudaGetSymbolAddress((void**)&wac, g_wac);
    cudaGetSymbolAddress((void**)&wpc, g_wpc);

    cudaFuncSetAttribute(gemm_f16<true>,  cudaFuncAttributeMaxDynamicSharedMemorySize, GEMM_SMEM);
    cudaFuncSetAttribute(gemm_f16<false>, cudaFuncAttributeMaxDynamicSharedMemorySize, GEMM_SMEM);
    cudaFuncSetAttribute(attn_f16, cudaFuncAttributeMaxDynamicSharedMemorySize, ATT_SMEM);

    round_f16<<<(M_ROWS * D_MODEL / 4 + 255) / 256, 256>>>(x, xc, M_ROWS * D_MODEL / 4);
    round_f16<<<(D3 * D_MODEL / 4 + 255) / 256, 256>>>(w_attn, wac, D3 * D_MODEL / 4);
    round_f16<<<(D_MODEL * D_MODEL / 4 + 255) / 256, 256>>>(w_proj, wpc, D_MODEL * D_MODEL / 4);

    dim3 g1(D3 / TBN, M_ROWS / TBM);
    gemm_f16<true><<<g1, 256, GEMM_SMEM>>>(xc, wac, qkv, M_ROWS, D3, D_MODEL);

    dim3 ga(S_LEN / 128, N_HEADS, BATCH);
    attn_f16<<<ga, 256, ATT_SMEM>>>(qkv, yb);

    dim3 g2(D_MODEL / TBN, M_ROWS / TBM);
    gemm_f16<false><<<g2, 256, GEMM_SMEM>>>(yb, wpc, out, M_ROWS, D_MODEL, D_MODEL);
}

// round 9
// speedup vs baseline: 1.1507x; 1.1507x over previous
#include <cuda_runtime.h>
#include <cuda_fp16.h>
#include <cstdint>
#include <cstddef>

// ---------------------------------------------------------------------------
// CausalSelfAttention: out = proj( causal_attn( x @ Wqkv^T ) )
// fp16 mma.sync m16n8k16. GEMM: 128x128, warp 64x32, 2 CTA/SM, single-sync
// 4-stage cp.async ring. Attention: fp16 flash, f16x2 exp, ones-MMA row sums.
// ---------------------------------------------------------------------------

#define BATCH   4
#define S_LEN   2048
#define D_MODEL 1024
#define D3      3072
#define N_HEADS 16
#define DH      64
#define M_ROWS  (BATCH * S_LEN)   // 8192

__device__ __half g_qkv[(size_t)M_ROWS * D3];
__device__ __half g_y[(size_t)M_ROWS * D_MODEL];
__device__ __half g_xc[(size_t)M_ROWS * D_MODEL];
__device__ __half g_wac[(size_t)D3 * D_MODEL];
__device__ __half g_wpc[(size_t)D_MODEL * D_MODEL];

// ---- helpers ----------------------------------------------------------------
__device__ __forceinline__ uint32_t pack_h2(float a, float b) {
    __half2 h = __floats2half2_rn(a, b);
    return *(uint32_t*)&h;
}
__device__ __forceinline__ float ex2f(float x) {
    float r;
    asm("ex2.approx.ftz.f32 %0, %1;" : "=f"(r) : "f"(x));
    return r;
}
__device__ __forceinline__ uint32_t h2ex2(uint32_t x) {
    uint32_t r;
    asm("ex2.approx.f16x2 %0, %1;" : "=r"(r) : "r"(x));
    return r;
}
__device__ __forceinline__ void ldsm_x4(uint32_t addr, uint32_t& r0, uint32_t& r1,
                                        uint32_t& r2, uint32_t& r3) {
    asm volatile("ldmatrix.sync.aligned.m8n8.x4.shared.b16 {%0,%1,%2,%3}, [%4];"
                 : "=r"(r0), "=r"(r1), "=r"(r2), "=r"(r3) : "r"(addr));
}
__device__ __forceinline__ void ldsm_x4t(uint32_t addr, uint32_t& r0, uint32_t& r1,
                                         uint32_t& r2, uint32_t& r3) {
    asm volatile("ldmatrix.sync.aligned.m8n8.x4.trans.shared.b16 {%0,%1,%2,%3}, [%4];"
                 : "=r"(r0), "=r"(r1), "=r"(r2), "=r"(r3) : "r"(addr));
}
__device__ __forceinline__ void mma_f16(float& c0, float& c1, float& c2, float& c3,
                                        uint32_t a0, uint32_t a1, uint32_t a2, uint32_t a3,
                                        uint32_t b0, uint32_t b1) {
    asm volatile("mma.sync.aligned.m16n8k16.row.col.f32.f16.f16.f32 "
                 "{%0,%1,%2,%3}, {%4,%5,%6,%7}, {%8,%9}, {%0,%1,%2,%3};"
                 : "+f"(c0), "+f"(c1), "+f"(c2), "+f"(c3)
                 : "r"(a0), "r"(a1), "r"(a2), "r"(a3), "r"(b0), "r"(b1));
}
__device__ __forceinline__ void cp16(uint32_t dst, const void* src) {
    asm volatile("cp.async.cg.shared.global [%0], [%1], 16;" :: "r"(dst), "l"(src));
}
#define CP_COMMIT() asm volatile("cp.async.commit_group;")
#define CP_WAIT(n)  asm volatile("cp.async.wait_group %0;" :: "n"(n))

__device__ __forceinline__ uint32_t smem_u32(const void* p) {
    return (uint32_t)__cvta_generic_to_shared(p);
}

// ---------------------------------------------------------------------------
// Pre-round fp32 -> fp16
// ---------------------------------------------------------------------------
__global__ void round_f16(const float* __restrict__ in, __half* __restrict__ out, int n4) {
    int i = blockIdx.x * blockDim.x + threadIdx.x;
    if (i < n4) {
        float4 v = ((const float4*)in)[i];
        uint2 r = {pack_h2(v.x, v.y), pack_h2(v.z, v.w)};
        ((uint2*)out)[i] = r;
    }
}

// ---------------------------------------------------------------------------
// fp16 GEMM (NT): C[M,N] = A[M,K] @ B[N,K]^T
// Block 128x128x(32 halfs); 8 warps 2x4; warp 64x32; 4-stage ring, ONE sync/iter.
// ---------------------------------------------------------------------------
#define TBM 128
#define TBN 128
#define TBKH 32
#define GSTG 4
#define G_STAGE_BYTES 16384
#define GEMM_SMEM (GSTG * G_STAGE_BYTES)   // 65536

template <bool HALF_OUT>
__global__ __launch_bounds__(256, 2)
void gemm_f16(const __half* __restrict__ A, const __half* __restrict__ B,
              void* __restrict__ Cv, int M, int N, int K) {
    extern __shared__ uint32_t sh[];

    const int tid    = threadIdx.x;
    const int lane   = tid & 31;
    const int warp   = tid >> 5;
    const int warp_m = warp >> 2;
    const int warp_n = warp & 3;
    const int row0   = blockIdx.y * TBM;
    const int col0   = blockIdx.x * TBN;

    const __half* Ab = A + (size_t)row0 * K;
    const __half* Bb = B + (size_t)col0 * K;

    const uint32_t base = smem_u32(sh);
    uint32_t sA[GSTG], sB[GSTG];
#pragma unroll
    for (int s = 0; s < GSTG; s++) { sA[s] = base + s * G_STAGE_BYTES; sB[s] = sA[s] + 8192; }

    const __half* a_src[2];
    const __half* b_src[2];
    uint32_t a_rel[2];
#pragma unroll
    for (int r = 0; r < 2; r++) {
        int idx = tid + 256 * r, row = idx >> 2, c = idx & 3;
        a_src[r] = Ab + (size_t)row * K + c * 8;
        b_src[r] = Bb + (size_t)row * K + c * 8;
        a_rel[r] = (uint32_t)(row * 64 + ((c ^ ((row >> 1) & 3)) << 4));
    }

    uint32_t a_off[4][2], b_off[2][2];
    {
        int mat = lane >> 3, r = lane & 7;
#pragma unroll
        for (int mt = 0; mt < 4; mt++)
#pragma unroll
            for (int ks = 0; ks < 2; ks++) {
                int row = warp_m * 64 + mt * 16 + ((mat & 1) << 3) + r;
                int ch  = ks * 2 + (mat >> 1);
                a_off[mt][ks] = (uint32_t)(row * 64 + ((ch ^ ((row >> 1) & 3)) << 4));
            }
#pragma unroll
        for (int ntp = 0; ntp < 2; ntp++)
#pragma unroll
            for (int ks = 0; ks < 2; ks++) {
                int row = warp_n * 32 + ntp * 16 + ((mat >> 1) << 3) + r;
                int ch  = ks * 2 + (mat & 1);
                b_off[ntp][ks] = (uint32_t)(row * 64 + ((ch ^ ((row >> 1) & 3)) << 4));
            }
    }

    float c[4][4][4];
#pragma unroll
    for (int i = 0; i < 4; i++)
#pragma unroll
        for (int j = 0; j < 4; j++)
#pragma unroll
            for (int q = 0; q < 4; q++) c[i][j][q] = 0.f;

    const int NIT = K / TBKH;   // 32

    // prologue: stages 0..2
#pragma unroll
    for (int s = 0; s < 3; s++) {
#pragma unroll
        for (int r = 0; r < 2; r++) {
            cp16(sA[s] + a_rel[r], a_src[r] + s * TBKH);
            cp16(sB[s] + a_rel[r], b_src[r] + s * TBKH);
        }
        CP_COMMIT();
    }

    int buf = 0, nxt = 3;
    for (int it = 0; it < NIT; it++) {
        CP_WAIT(2);
        __syncthreads();   // stage `buf` ready; all warps done reading stage `nxt` (iter it-1)

        if (it + 3 < NIT) {
            const int k0 = (it + 3) * TBKH;
#pragma unroll
            for (int r = 0; r < 2; r++) {
                cp16(sA[nxt] + a_rel[r], a_src[r] + k0);
                cp16(sB[nxt] + a_rel[r], b_src[r] + k0);
            }
        }
        CP_COMMIT();

#pragma unroll
        for (int ks = 0; ks < 2; ks++) {
            uint32_t af[4][4];
#pragma unroll
            for (int mt = 0; mt < 4; mt++)
                ldsm_x4(sA[buf] + a_off[mt][ks], af[mt][0], af[mt][1], af[mt][2], af[mt][3]);
            uint32_t bf[2][4];
#pragma unroll
            for (int ntp = 0; ntp < 2; ntp++)
                ldsm_x4(sB[buf] + b_off[ntp][ks], bf[ntp][0], bf[ntp][1], bf[ntp][2], bf[ntp][3]);
#pragma unroll
            for (int mt = 0; mt < 4; mt++)
#pragma unroll
                for (int nt = 0; nt < 4; nt++) {
                    const uint32_t* bp = &bf[nt >> 1][(nt & 1) * 2];
                    mma_f16(c[mt][nt][0], c[mt][nt][1], c[mt][nt][2], c[mt][nt][3],
                            af[mt][0], af[mt][1], af[mt][2], af[mt][3], bp[0], bp[1]);
                }
        }
        buf = (buf + 1) & (GSTG - 1);
        nxt = (nxt + 1) & (GSTG - 1);
    }

    const int rql = lane >> 2;
    const int cpl = (lane & 3) * 2;
#pragma unroll
    for (int mt = 0; mt < 4; mt++) {
        int rg = row0 + warp_m * 64 + mt * 16 + rql;
#pragma unroll
        for (int nt = 0; nt < 4; nt++) {
            int cg = col0 + warp_n * 32 + nt * 8 + cpl;
            if (HALF_OUT) {
                __half* C = (__half*)Cv;
                *(uint32_t*)(C + (size_t)rg * N + cg)       = pack_h2(c[mt][nt][0], c[mt][nt][1]);
                *(uint32_t*)(C + (size_t)(rg + 8) * N + cg) = pack_h2(c[mt][nt][2], c[mt][nt][3]);
            } else {
                float* C = (float*)Cv;
                float2 v0 = {c[mt][nt][0], c[mt][nt][1]};
                float2 v1 = {c[mt][nt][2], c[mt][nt][3]};
                *(float2*)(C + (size_t)rg * N + cg)       = v0;
                *(float2*)(C + (size_t)(rg + 8) * N + cg) = v1;
            }
        }
    }
}

// ---------------------------------------------------------------------------
// fp16 causal flash attention: f16x2 exponentials + ones-MMA row sums.
// ---------------------------------------------------------------------------
#define ATT_SCALE 0.18033688f
#define ATT_SMEM  49152
#define ONES_H2   0x3C003C00u

__global__ __launch_bounds__(256, 2)
void attn_f16(const __half* __restrict__ qkv, __half* __restrict__ y) {
    extern __shared__ uint32_t smu[];
    char* smc = (char*)smu;
    const uint32_t qs_base = smem_u32(smu);
    const uint32_t ks_base = qs_base + 16384;
    const uint32_t vs_base = ks_base + 16384;

    const int tid  = threadIdx.x;
    const int lane = tid & 31;
    const int w    = tid >> 5;
    const int qi   = (S_LEN / 128 - 1) - blockIdx.x;
    const int h    = blockIdx.y;
    const int b    = blockIdx.z;
    const int q0   = qi * 128;

    const __half* qb = qkv + (size_t)b * S_LEN * D3 + h * DH;
    const __half* kb = qb + D_MODEL;
    const __half* vb = qb + 2 * D_MODEL;

    int l_row[2], l_chk[2];
    uint32_t l_rel[2];
#pragma unroll
    for (int r = 0; r < 2; r++) {
        int idx = tid + 256 * r;
        l_row[r] = idx >> 3; l_chk[r] = idx & 7;
        l_rel[r] = (uint32_t)(l_row[r] * 128 + ((l_chk[r] ^ (l_row[r] & 7)) << 4));
    }

#pragma unroll
    for (int r = 0; r < 2; r++) {
        cp16(ks_base + l_rel[r], kb + (size_t)l_row[r] * D3 + l_chk[r] * 8);
        cp16(vs_base + l_rel[r], vb + (size_t)l_row[r] * D3 + l_chk[r] * 8);
    }
    CP_COMMIT();

#pragma unroll
    for (int r = 0; r < 4; r++) {
        int idx = tid + 256 * r, row = idx >> 3, ch = idx & 7;
        uint4 raw = *(const uint4*)(qb + (size_t)(q0 + row) * D3 + ch * 8);
        uint32_t* rp = (uint32_t*)&raw;
        uint4 outv;
        uint32_t* op = (uint32_t*)&outv;
#pragma unroll
        for (int j = 0; j < 4; j++) {
            __half2 hv = *(__half2*)&rp[j];
            float2 f = __half22float2(hv);
            op[j] = pack_h2(f.x * ATT_SCALE, f.y * ATT_SCALE);
        }
        *(uint4*)(smc + row * 128 + ((ch ^ (row & 7)) << 4)) = outv;
    }
    CP_WAIT(0);
    __syncthreads();

    const int mat = lane >> 3, rr = lane & 7;
    uint32_t qf[4][4];
    {
        int rowA = w * 16 + ((mat & 1) << 3) + rr;
        int rbase = rowA * 128;
        int rx = rowA & 7;
#pragma unroll
        for (int ks = 0; ks < 4; ks++) {
            int ch = ks * 2 + (mat >> 1);
            ldsm_x4(qs_base + rbase + ((ch ^ rx) << 4), qf[ks][0], qf[ks][1], qf[ks][2], qf[ks][3]);
        }
    }
    uint32_t krowOff[4]; int krx[4];
#pragma unroll
    for (int ntp = 0; ntp < 4; ntp++) {
        int rowB = ntp * 16 + ((mat >> 1) << 3) + rr;
        krowOff[ntp] = (uint32_t)(rowB * 128);
        krx[ntp] = rowB & 7;
    }
    const int kbit = mat & 1;
    uint32_t vrowOff[4]; int vrx[4];
#pragma unroll
    for (int kt = 0; kt < 4; kt++) {
        int rowV = kt * 16 + ((mat & 1) << 3) + rr;
        vrowOff[kt] = (uint32_t)(rowV * 128);
        vrx[kt] = rowV & 7;
    }
    const int vbit = mat >> 1;

    float m_lo = -1e30f, m_hi = -1e30f, l_lo = 0.f, l_hi = 0.f;
    float co[8][4];
#pragma unroll
    for (int i = 0; i < 8; i++)
#pragma unroll
        for (int q = 0; q < 4; q++) co[i][q] = 0.f;

    const int rlo  = q0 + w * 16 + (lane >> 2);
    const int jsel = lane & 3;

    const int njb = 2 * qi + 2;
    int buf = 0;

    for (int jb = 0; jb < njb; jb++) {
        if (jb + 1 < njb) {
            const int kn = (jb + 1) * 64;
            const uint32_t kd = ks_base + (buf ^ 1) * 8192;
            const uint32_t vd = vs_base + (buf ^ 1) * 8192;
#pragma unroll
            for (int r = 0; r < 2; r++) {
                cp16(kd + l_rel[r], kb + (size_t)(kn + l_row[r]) * D3 + l_chk[r] * 8);
                cp16(vd + l_rel[r], vb + (size_t)(kn + l_row[r]) * D3 + l_chk[r] * 8);
            }
        }
        CP_COMMIT();

        const uint32_t kbuf = ks_base + (uint32_t)(buf * 8192);
        const uint32_t vbuf = vs_base + (uint32_t)(buf * 8192);

        // ---- S = Q @ K^T ----
        float cs[8][4];
#pragma unroll
        for (int i = 0; i < 8; i++)
#pragma unroll
            for (int q = 0; q < 4; q++) cs[i][q] = 0.f;

#pragma unroll
        for (int ks = 0; ks < 4; ks++) {
            uint32_t bf[4][4];
            int ch = ks * 2 + kbit;
#pragma unroll
            for (int ntp = 0; ntp < 4; ntp++)
                ldsm_x4(kbuf + krowOff[ntp] + ((ch ^ krx[ntp]) << 4),
                        bf[ntp][0], bf[ntp][1], bf[ntp][2], bf[ntp][3]);
#pragma unroll
            for (int nt = 0; nt < 8; nt++) {
                const uint32_t* bp = &bf[nt >> 1][(nt & 1) * 2];
                mma_f16(cs[nt][0], cs[nt][1], cs[nt][2], cs[nt][3],
                        qf[ks][0], qf[ks][1], qf[ks][2], qf[ks][3], bp[0], bp[1]);
            }
        }

        // ---- causal mask ----
        if (jb * 64 >= q0) {
#pragma unroll
            for (int nt = 0; nt < 8; nt++) {
                int cb = jb * 64 + nt * 8 + 2 * jsel;
                if (cb     > rlo)     cs[nt][0] = -1e30f;
                if (cb + 1 > rlo)     cs[nt][1] = -1e30f;
                if (cb     > rlo + 8) cs[nt][2] = -1e30f;
                if (cb + 1 > rlo + 8) cs[nt][3] = -1e30f;
            }
        }

        // ---- online softmax (base-2); P computed directly in fp16x2 ----
        float ml = -1e30f, mh = -1e30f;
#pragma unroll
        for (int nt = 0; nt < 8; nt++) {
            ml = fmaxf(ml, fmaxf(cs[nt][0], cs[nt][1]));
            mh = fmaxf(mh, fmaxf(cs[nt][2], cs[nt][3]));
        }
        ml = fmaxf(ml, __shfl_xor_sync(0xffffffffu, ml, 1));
        ml = fmaxf(ml, __shfl_xor_sync(0xffffffffu, ml, 2));
        mh = fmaxf(mh, __shfl_xor_sync(0xffffffffu, mh, 1));
        mh = fmaxf(mh, __shfl_xor_sync(0xffffffffu, mh, 2));
        float Ml = fmaxf(m_lo, ml), Mh = fmaxf(m_hi, mh);
        float al = ex2f(m_lo - Ml), ah = ex2f(m_hi - Mh);
        m_lo = Ml; m_hi = Mh;

        uint32_t pp[8][2];
#pragma unroll
        for (int nt = 0; nt < 8; nt++) {
            pp[nt][0] = h2ex2(pack_h2(cs[nt][0] - Ml, cs[nt][1] - Ml));
            pp[nt][1] = h2ex2(pack_h2(cs[nt][2] - Mh, cs[nt][3] - Mh));
        }

        // row sums via tensor core: csum = P @ ones
        float csum0 = 0.f, csum1 = 0.f, csum2 = 0.f, csum3 = 0.f;
#pragma unroll
        for (int kt = 0; kt < 4; kt++)
            mma_f16(csum0, csum1, csum2, csum3,
                    pp[2 * kt][0], pp[2 * kt][1], pp[2 * kt + 1][0], pp[2 * kt + 1][1],
                    ONES_H2, ONES_H2);
        l_lo = l_lo * al + csum0;
        l_hi = l_hi * ah + csum2;

#pragma unroll
        for (int i = 0; i < 8; i++) {
            co[i][0] *= al; co[i][1] *= al; co[i][2] *= ah; co[i][3] *= ah;
        }

        // ---- O += P @ V ----
#pragma unroll
        for (int kt = 0; kt < 4; kt++) {
            uint32_t pa0 = pp[2 * kt][0];
            uint32_t pa1 = pp[2 * kt][1];
            uint32_t pa2 = pp[2 * kt + 1][0];
            uint32_t pa3 = pp[2 * kt + 1][1];

#pragma unroll
            for (int ntp = 0; ntp < 4; ntp++) {
                uint32_t bf0, bf1, bf2, bf3;
                int ch = ntp * 2 + vbit;
                ldsm_x4t(vbuf + vrowOff[kt] + ((ch ^ vrx[kt]) << 4), bf0, bf1, bf2, bf3);
                mma_f16(co[2 * ntp][0], co[2 * ntp][1], co[2 * ntp][2], co[2 * ntp][3],
                        pa0, pa1, pa2, pa3, bf0, bf1);
                mma_f16(co[2 * ntp + 1][0], co[2 * ntp + 1][1], co[2 * ntp + 1][2], co[2 * ntp + 1][3],
                        pa0, pa1, pa2, pa3, bf2, bf3);
            }
        }

        CP_WAIT(0);
        __syncthreads();
        buf ^= 1;
    }

    const float il = 1.0f / l_lo, ih = 1.0f / l_hi;
    __half* yb = y + ((size_t)b * S_LEN + q0 + w * 16 + (lane >> 2)) * D_MODEL + h * DH + 2 * jsel;
#pragma unroll
    for (int nt = 0; nt < 8; nt++) {
        *(uint32_t*)(yb + nt * 8)                       = pack_h2(co[nt][0] * il, co[nt][1] * il);
        *(uint32_t*)(yb + nt * 8 + 8 * (size_t)D_MODEL) = pack_h2(co[nt][2] * ih, co[nt][3] * ih);
    }
}

// ---------------------------------------------------------------------------
extern "C" void kernel_launch(void* const* d_in, const int* in_sizes, int n_in,
                              void* d_out, int out_size) {
    const float* x      = (const float*)d_in[0];
    const float* w_attn = (const float*)d_in[1];
    const float* w_proj = (const float*)d_in[2];
    float* out = (float*)d_out;

    __half *qkv, *yb, *xc, *wac, *wpc;
    cudaGetSymbolAddress((void**)&qkv, g_qkv);
    cudaGetSymbolAddress((void**)&yb, g_y);
    cudaGetSymbolAddress((void**)&xc, g_xc);
    cudaGetSymbolAddress((void**)&wac, g_wac);
    cudaGetSymbolAddress((void**)&wpc, g_wpc);

    cudaFuncSetAttribute(gemm_f16<true>,  cudaFuncAttributeMaxDynamicSharedMemorySize, GEMM_SMEM);
    cudaFuncSetAttribute(gemm_f16<false>, cudaFuncAttributeMaxDynamicSharedMemorySize, GEMM_SMEM);
    cudaFuncSetAttribute(attn_f16, cudaFuncAttributeMaxDynamicSharedMemorySize, ATT_SMEM);

    round_f16<<<(M_ROWS * D_MODEL / 4 + 255) / 256, 256>>>(x, xc, M_ROWS * D_MODEL / 4);
    round_f16<<<(D3 * D_MODEL / 4 + 255) / 256, 256>>>(w_attn, wac, D3 * D_MODEL / 4);
    round_f16<<<(D_MODEL * D_MODEL / 4 + 255) / 256, 256>>>(w_proj, wpc, D_MODEL * D_MODEL / 4);

    dim3 g1(D3 / TBN, M_ROWS / TBM);
    gemm_f16<true><<<g1, 256, GEMM_SMEM>>>(xc, wac, qkv, M_ROWS, D3, D_MODEL);

    dim3 ga(S_LEN / 128, N_HEADS, BATCH);
    attn_f16<<<ga, 256, ATT_SMEM>>>(qkv, yb);

    dim3 g2(D_MODEL / TBN, M_ROWS / TBM);
    gemm_f16<false><<<g2, 256, GEMM_SMEM>>>(yb, wpc, out, M_ROWS, D_MODEL, D_MODEL);
}

// round 11
// speedup vs baseline: 1.1750x; 1.0211x over previous
#include <cuda_runtime.h>
#include <cuda_fp16.h>
#include <cstdint>
#include <cstddef>

// ---------------------------------------------------------------------------
// CausalSelfAttention: out = proj( causal_attn( x @ Wqkv^T ) )
// fp16 mma.sync m16n8k16. GEMM: 128x128, warp 64x32, 2 CTA/SM, 4-stage ring
// (R9-proven wait->sync->prefetch ordering). Attention: fp16 flash, f16x2 exp,
// ones-MMA row sums, 3-stage K/V pipeline. Fused pre-round kernel.
// ---------------------------------------------------------------------------

#define BATCH   4
#define S_LEN   2048
#define D_MODEL 1024
#define D3      3072
#define N_HEADS 16
#define DH      64
#define M_ROWS  (BATCH * S_LEN)   // 8192

__device__ __half g_qkv[(size_t)M_ROWS * D3];
__device__ __half g_y[(size_t)M_ROWS * D_MODEL];
__device__ __half g_xc[(size_t)M_ROWS * D_MODEL];
__device__ __half g_wac[(size_t)D3 * D_MODEL];
__device__ __half g_wpc[(size_t)D_MODEL * D_MODEL];

// ---- helpers ----------------------------------------------------------------
__device__ __forceinline__ uint32_t pack_h2(float a, float b) {
    __half2 h = __floats2half2_rn(a, b);
    return *(uint32_t*)&h;
}
__device__ __forceinline__ float ex2f(float x) {
    float r;
    asm("ex2.approx.ftz.f32 %0, %1;" : "=f"(r) : "f"(x));
    return r;
}
__device__ __forceinline__ uint32_t h2ex2(uint32_t x) {
    uint32_t r;
    asm("ex2.approx.f16x2 %0, %1;" : "=r"(r) : "r"(x));
    return r;
}
__device__ __forceinline__ void ldsm_x4(uint32_t addr, uint32_t& r0, uint32_t& r1,
                                        uint32_t& r2, uint32_t& r3) {
    asm volatile("ldmatrix.sync.aligned.m8n8.x4.shared.b16 {%0,%1,%2,%3}, [%4];"
                 : "=r"(r0), "=r"(r1), "=r"(r2), "=r"(r3) : "r"(addr));
}
__device__ __forceinline__ void ldsm_x4t(uint32_t addr, uint32_t& r0, uint32_t& r1,
                                         uint32_t& r2, uint32_t& r3) {
    asm volatile("ldmatrix.sync.aligned.m8n8.x4.trans.shared.b16 {%0,%1,%2,%3}, [%4];"
                 : "=r"(r0), "=r"(r1), "=r"(r2), "=r"(r3) : "r"(addr));
}
__device__ __forceinline__ void mma_f16(float& c0, float& c1, float& c2, float& c3,
                                        uint32_t a0, uint32_t a1, uint32_t a2, uint32_t a3,
                                        uint32_t b0, uint32_t b1) {
    asm volatile("mma.sync.aligned.m16n8k16.row.col.f32.f16.f16.f32 "
                 "{%0,%1,%2,%3}, {%4,%5,%6,%7}, {%8,%9}, {%0,%1,%2,%3};"
                 : "+f"(c0), "+f"(c1), "+f"(c2), "+f"(c3)
                 : "r"(a0), "r"(a1), "r"(a2), "r"(a3), "r"(b0), "r"(b1));
}
__device__ __forceinline__ void cp16(uint32_t dst, const void* src) {
    asm volatile("cp.async.cg.shared.global [%0], [%1], 16;" :: "r"(dst), "l"(src));
}
#define CP_COMMIT() asm volatile("cp.async.commit_group;")
#define CP_WAIT(n)  asm volatile("cp.async.wait_group %0;" :: "n"(n))

__device__ __forceinline__ uint32_t smem_u32(const void* p) {
    return (uint32_t)__cvta_generic_to_shared(p);
}

// ---------------------------------------------------------------------------
// Fused pre-round fp32 -> fp16 for x, w_attn, w_proj (one launch)
// ---------------------------------------------------------------------------
#define XC_N4  (M_ROWS * D_MODEL / 4)
#define WAC_N4 (D3 * D_MODEL / 4)
#define WPC_N4 (D_MODEL * D_MODEL / 4)
#define RND_TOTAL (XC_N4 + WAC_N4 + WPC_N4)

__global__ void round_all(const float* __restrict__ x, const float* __restrict__ wa,
                          const float* __restrict__ wp) {
    int i = blockIdx.x * blockDim.x + threadIdx.x;
    if (i >= RND_TOTAL) return;
    const float* src;
    __half* dst;
    int j;
    if (i < XC_N4)                { src = x;  dst = g_xc;  j = i; }
    else if (i < XC_N4 + WAC_N4)  { src = wa; dst = g_wac; j = i - XC_N4; }
    else                          { src = wp; dst = g_wpc; j = i - XC_N4 - WAC_N4; }
    float4 v = ((const float4*)src)[j];
    uint2 r = {pack_h2(v.x, v.y), pack_h2(v.z, v.w)};
    ((uint2*)dst)[j] = r;
}

// ---------------------------------------------------------------------------
// fp16 GEMM (NT): C[M,N] = A[M,K] @ B[N,K]^T
// Block 128x128x(32 halfs); 8 warps 2x4; warp 64x32; 4-stage ring.
// R9-proven ordering: CP_WAIT(2) -> sync -> prefetch -> commit -> compute.
// ---------------------------------------------------------------------------
#define TBM 128
#define TBN 128
#define TBKH 32
#define GSTG 4
#define G_STAGE_BYTES 16384
#define GEMM_SMEM (GSTG * G_STAGE_BYTES)   // 65536

template <bool HALF_OUT>
__global__ __launch_bounds__(256, 2)
void gemm_f16(const __half* __restrict__ A, const __half* __restrict__ B,
              void* __restrict__ Cv, int M, int N, int K) {
    extern __shared__ uint32_t sh[];

    const int tid    = threadIdx.x;
    const int lane   = tid & 31;
    const int warp   = tid >> 5;
    const int warp_m = warp >> 2;
    const int warp_n = warp & 3;
    const int row0   = blockIdx.y * TBM;
    const int col0   = blockIdx.x * TBN;

    const __half* Ab = A + (size_t)row0 * K;
    const __half* Bb = B + (size_t)col0 * K;

    const uint32_t base = smem_u32(sh);
    uint32_t sA[GSTG], sB[GSTG];
#pragma unroll
    for (int s = 0; s < GSTG; s++) { sA[s] = base + s * G_STAGE_BYTES; sB[s] = sA[s] + 8192; }

    const __half* a_src[2];
    const __half* b_src[2];
    uint32_t a_rel[2];
#pragma unroll
    for (int r = 0; r < 2; r++) {
        int idx = tid + 256 * r, row = idx >> 2, c = idx & 3;
        a_src[r] = Ab + (size_t)row * K + c * 8;
        b_src[r] = Bb + (size_t)row * K + c * 8;
        a_rel[r] = (uint32_t)(row * 64 + ((c ^ ((row >> 1) & 3)) << 4));
    }

    uint32_t a_off[4][2], b_off[2][2];
    {
        int mat = lane >> 3, r = lane & 7;
#pragma unroll
        for (int mt = 0; mt < 4; mt++)
#pragma unroll
            for (int ks = 0; ks < 2; ks++) {
                int row = warp_m * 64 + mt * 16 + ((mat & 1) << 3) + r;
                int ch  = ks * 2 + (mat >> 1);
                a_off[mt][ks] = (uint32_t)(row * 64 + ((ch ^ ((row >> 1) & 3)) << 4));
            }
#pragma unroll
        for (int ntp = 0; ntp < 2; ntp++)
#pragma unroll
            for (int ks = 0; ks < 2; ks++) {
                int row = warp_n * 32 + ntp * 16 + ((mat >> 1) << 3) + r;
                int ch  = ks * 2 + (mat & 1);
                b_off[ntp][ks] = (uint32_t)(row * 64 + ((ch ^ ((row >> 1) & 3)) << 4));
            }
    }

    float c[4][4][4];
#pragma unroll
    for (int i = 0; i < 4; i++)
#pragma unroll
        for (int j = 0; j < 4; j++)
#pragma unroll
            for (int q = 0; q < 4; q++) c[i][j][q] = 0.f;

    const int NIT = K / TBKH;   // 32

    // prologue: stages 0..2
#pragma unroll
    for (int s = 0; s < 3; s++) {
#pragma unroll
        for (int r = 0; r < 2; r++) {
            cp16(sA[s] + a_rel[r], a_src[r] + s * TBKH);
            cp16(sB[s] + a_rel[r], b_src[r] + s * TBKH);
        }
        CP_COMMIT();
    }

    int buf = 0, nxt = 3;
    for (int it = 0; it < NIT; it++) {
        CP_WAIT(2);
        __syncthreads();   // stage `buf` visible to all; readers of slot `nxt` done

        if (it + 3 < NIT) {
            const int k0 = (it + 3) * TBKH;
#pragma unroll
            for (int r = 0; r < 2; r++) {
                cp16(sA[nxt] + a_rel[r], a_src[r] + k0);
                cp16(sB[nxt] + a_rel[r], b_src[r] + k0);
            }
        }
        CP_COMMIT();

#pragma unroll
        for (int ks = 0; ks < 2; ks++) {
            uint32_t af[4][4];
#pragma unroll
            for (int mt = 0; mt < 4; mt++)
                ldsm_x4(sA[buf] + a_off[mt][ks], af[mt][0], af[mt][1], af[mt][2], af[mt][3]);
            uint32_t bf[2][4];
#pragma unroll
            for (int ntp = 0; ntp < 2; ntp++)
                ldsm_x4(sB[buf] + b_off[ntp][ks], bf[ntp][0], bf[ntp][1], bf[ntp][2], bf[ntp][3]);
#pragma unroll
            for (int mt = 0; mt < 4; mt++)
#pragma unroll
                for (int nt = 0; nt < 4; nt++) {
                    const uint32_t* bp = &bf[nt >> 1][(nt & 1) * 2];
                    mma_f16(c[mt][nt][0], c[mt][nt][1], c[mt][nt][2], c[mt][nt][3],
                            af[mt][0], af[mt][1], af[mt][2], af[mt][3], bp[0], bp[1]);
                }
        }
        buf = (buf + 1) & (GSTG - 1);
        nxt = (nxt + 1) & (GSTG - 1);
    }

    const int rql = lane >> 2;
    const int cpl = (lane & 3) * 2;
#pragma unroll
    for (int mt = 0; mt < 4; mt++) {
        int rg = row0 + warp_m * 64 + mt * 16 + rql;
#pragma unroll
        for (int nt = 0; nt < 4; nt++) {
            int cg = col0 + warp_n * 32 + nt * 8 + cpl;
            if (HALF_OUT) {
                __half* C = (__half*)Cv;
                *(uint32_t*)(C + (size_t)rg * N + cg)       = pack_h2(c[mt][nt][0], c[mt][nt][1]);
                *(uint32_t*)(C + (size_t)(rg + 8) * N + cg) = pack_h2(c[mt][nt][2], c[mt][nt][3]);
            } else {
                float* C = (float*)Cv;
                float2 v0 = {c[mt][nt][0], c[mt][nt][1]};
                float2 v1 = {c[mt][nt][2], c[mt][nt][3]};
                *(float2*)(C + (size_t)rg * N + cg)       = v0;
                *(float2*)(C + (size_t)(rg + 8) * N + cg) = v1;
            }
        }
    }
}

// ---------------------------------------------------------------------------
// fp16 causal flash attention: f16x2 exp + ones-MMA row sums.
// 3-stage K/V cp.async ring, ordering: wait(1) -> sync -> prefetch -> compute.
// SMEM: Q 16K + K 3x8K + V 3x8K = 64KB.
// ---------------------------------------------------------------------------
#define ATT_SCALE 0.18033688f
#define ATT_SMEM  65536
#define ONES_H2   0x3C003C00u

__global__ __launch_bounds__(256, 2)
void attn_f16(const __half* __restrict__ qkv, __half* __restrict__ y) {
    extern __shared__ uint32_t smu[];
    char* smc = (char*)smu;
    const uint32_t qs_base = smem_u32(smu);
    const uint32_t ks_base = qs_base + 16384;           // 3 stages of 8KB
    const uint32_t vs_base = ks_base + 3 * 8192;        // 3 stages of 8KB

    const int tid  = threadIdx.x;
    const int lane = tid & 31;
    const int w    = tid >> 5;
    const int qi   = (S_LEN / 128 - 1) - blockIdx.x;
    const int h    = blockIdx.y;
    const int b    = blockIdx.z;
    const int q0   = qi * 128;

    const __half* qb = qkv + (size_t)b * S_LEN * D3 + h * DH;
    const __half* kb = qb + D_MODEL;
    const __half* vb = qb + 2 * D_MODEL;

    int l_row[2], l_chk[2];
    uint32_t l_rel[2];
#pragma unroll
    for (int r = 0; r < 2; r++) {
        int idx = tid + 256 * r;
        l_row[r] = idx >> 3; l_chk[r] = idx & 7;
        l_rel[r] = (uint32_t)(l_row[r] * 128 + ((l_chk[r] ^ (l_row[r] & 7)) << 4));
    }

    const int njb = 2 * qi + 2;   // >= 2 always

    // prologue: issue K/V tiles 0 and 1 (two commit groups)
#pragma unroll
    for (int s = 0; s < 2; s++) {
        const int kn = s * 64;
        const uint32_t kd = ks_base + s * 8192;
        const uint32_t vd = vs_base + s * 8192;
#pragma unroll
        for (int r = 0; r < 2; r++) {
            cp16(kd + l_rel[r], kb + (size_t)(kn + l_row[r]) * D3 + l_chk[r] * 8);
            cp16(vd + l_rel[r], vb + (size_t)(kn + l_row[r]) * D3 + l_chk[r] * 8);
        }
        CP_COMMIT();
    }

    // load Q (scale, fp16) into smem
#pragma unroll
    for (int r = 0; r < 4; r++) {
        int idx = tid + 256 * r, row = idx >> 3, ch = idx & 7;
        uint4 raw = *(const uint4*)(qb + (size_t)(q0 + row) * D3 + ch * 8);
        uint32_t* rp = (uint32_t*)&raw;
        uint4 outv;
        uint32_t* op = (uint32_t*)&outv;
#pragma unroll
        for (int j = 0; j < 4; j++) {
            __half2 hv = *(__half2*)&rp[j];
            float2 f = __half22float2(hv);
            op[j] = pack_h2(f.x * ATT_SCALE, f.y * ATT_SCALE);
        }
        *(uint4*)(smc + row * 128 + ((ch ^ (row & 7)) << 4)) = outv;
    }
    __syncthreads();   // Q visible for ldsm

    const int mat = lane >> 3, rr = lane & 7;
    uint32_t qf[4][4];
    {
        int rowA = w * 16 + ((mat & 1) << 3) + rr;
        int rbase = rowA * 128;
        int rx = rowA & 7;
#pragma unroll
        for (int ks = 0; ks < 4; ks++) {
            int ch = ks * 2 + (mat >> 1);
            ldsm_x4(qs_base + rbase + ((ch ^ rx) << 4), qf[ks][0], qf[ks][1], qf[ks][2], qf[ks][3]);
        }
    }
    uint32_t krowOff[4]; int krx[4];
#pragma unroll
    for (int ntp = 0; ntp < 4; ntp++) {
        int rowB = ntp * 16 + ((mat >> 1) << 3) + rr;
        krowOff[ntp] = (uint32_t)(rowB * 128);
        krx[ntp] = rowB & 7;
    }
    const int kbit = mat & 1;
    uint32_t vrowOff[4]; int vrx[4];
#pragma unroll
    for (int kt = 0; kt < 4; kt++) {
        int rowV = kt * 16 + ((mat & 1) << 3) + rr;
        vrowOff[kt] = (uint32_t)(rowV * 128);
        vrx[kt] = rowV & 7;
    }
    const int vbit = mat >> 1;

    float m_lo = -1e30f, m_hi = -1e30f, l_lo = 0.f, l_hi = 0.f;
    float co[8][4];
#pragma unroll
    for (int i = 0; i < 8; i++)
#pragma unroll
        for (int q = 0; q < 4; q++) co[i][q] = 0.f;

    const int rlo  = q0 + w * 16 + (lane >> 2);
    const int jsel = lane & 3;

    int sbuf = 0;   // stage of tile jb

    for (int jb = 0; jb < njb; jb++) {
        CP_WAIT(1);        // tile jb landed (FIFO groups; 2 pending at loop top)
        __syncthreads();   // visibility + readers of reused slot are done

        // prefetch tile jb+2 into slot (jb+2)%3
        if (jb + 2 < njb) {
            const int kn = (jb + 2) * 64;
            const int ns = (sbuf + 2 >= 3) ? (sbuf - 1) : (sbuf + 2);
            const uint32_t kd = ks_base + ns * 8192;
            const uint32_t vd = vs_base + ns * 8192;
#pragma unroll
            for (int r = 0; r < 2; r++) {
                cp16(kd + l_rel[r], kb + (size_t)(kn + l_row[r]) * D3 + l_chk[r] * 8);
                cp16(vd + l_rel[r], vb + (size_t)(kn + l_row[r]) * D3 + l_chk[r] * 8);
            }
        }
        CP_COMMIT();

        const uint32_t kbuf = ks_base + (uint32_t)(sbuf * 8192);
        const uint32_t vbuf = vs_base + (uint32_t)(sbuf * 8192);

        // ---- S = Q @ K^T ----
        float cs[8][4];
#pragma unroll
        for (int i = 0; i < 8; i++)
#pragma unroll
            for (int q = 0; q < 4; q++) cs[i][q] = 0.f;

#pragma unroll
        for (int ks = 0; ks < 4; ks++) {
            uint32_t bf[4][4];
            int ch = ks * 2 + kbit;
#pragma unroll
            for (int ntp = 0; ntp < 4; ntp++)
                ldsm_x4(kbuf + krowOff[ntp] + ((ch ^ krx[ntp]) << 4),
                        bf[ntp][0], bf[ntp][1], bf[ntp][2], bf[ntp][3]);
#pragma unroll
            for (int nt = 0; nt < 8; nt++) {
                const uint32_t* bp = &bf[nt >> 1][(nt & 1) * 2];
                mma_f16(cs[nt][0], cs[nt][1], cs[nt][2], cs[nt][3],
                        qf[ks][0], qf[ks][1], qf[ks][2], qf[ks][3], bp[0], bp[1]);
            }
        }

        // ---- causal mask ----
        if (jb * 64 >= q0) {
#pragma unroll
            for (int nt = 0; nt < 8; nt++) {
                int cb = jb * 64 + nt * 8 + 2 * jsel;
                if (cb     > rlo)     cs[nt][0] = -1e30f;
                if (cb + 1 > rlo)     cs[nt][1] = -1e30f;
                if (cb     > rlo + 8) cs[nt][2] = -1e30f;
                if (cb + 1 > rlo + 8) cs[nt][3] = -1e30f;
            }
        }

        // ---- online softmax (base-2); P in fp16x2 ----
        float ml = -1e30f, mh = -1e30f;
#pragma unroll
        for (int nt = 0; nt < 8; nt++) {
            ml = fmaxf(ml, fmaxf(cs[nt][0], cs[nt][1]));
            mh = fmaxf(mh, fmaxf(cs[nt][2], cs[nt][3]));
        }
        ml = fmaxf(ml, __shfl_xor_sync(0xffffffffu, ml, 1));
        ml = fmaxf(ml, __shfl_xor_sync(0xffffffffu, ml, 2));
        mh = fmaxf(mh, __shfl_xor_sync(0xffffffffu, mh, 1));
        mh = fmaxf(mh, __shfl_xor_sync(0xffffffffu, mh, 2));
        float Ml = fmaxf(m_lo, ml), Mh = fmaxf(m_hi, mh);
        float al = ex2f(m_lo - Ml), ah = ex2f(m_hi - Mh);
        m_lo = Ml; m_hi = Mh;

        uint32_t pp[8][2];
#pragma unroll
        for (int nt = 0; nt < 8; nt++) {
            pp[nt][0] = h2ex2(pack_h2(cs[nt][0] - Ml, cs[nt][1] - Ml));
            pp[nt][1] = h2ex2(pack_h2(cs[nt][2] - Mh, cs[nt][3] - Mh));
        }

        // row sums via tensor core: csum = P @ ones
        float csum0 = 0.f, csum1 = 0.f, csum2 = 0.f, csum3 = 0.f;
#pragma unroll
        for (int kt = 0; kt < 4; kt++)
            mma_f16(csum0, csum1, csum2, csum3,
                    pp[2 * kt][0], pp[2 * kt][1], pp[2 * kt + 1][0], pp[2 * kt + 1][1],
                    ONES_H2, ONES_H2);
        l_lo = l_lo * al + csum0;
        l_hi = l_hi * ah + csum2;

#pragma unroll
        for (int i = 0; i < 8; i++) {
            co[i][0] *= al; co[i][1] *= al; co[i][2] *= ah; co[i][3] *= ah;
        }

        // ---- O += P @ V ----
#pragma unroll
        for (int kt = 0; kt < 4; kt++) {
            uint32_t pa0 = pp[2 * kt][0];
            uint32_t pa1 = pp[2 * kt][1];
            uint32_t pa2 = pp[2 * kt + 1][0];
            uint32_t pa3 = pp[2 * kt + 1][1];

#pragma unroll
            for (int ntp = 0; ntp < 4; ntp++) {
                uint32_t bf0, bf1, bf2, bf3;
                int ch = ntp * 2 + vbit;
                ldsm_x4t(vbuf + vrowOff[kt] + ((ch ^ vrx[kt]) << 4), bf0, bf1, bf2, bf3);
                mma_f16(co[2 * ntp][0], co[2 * ntp][1], co[2 * ntp][2], co[2 * ntp][3],
                        pa0, pa1, pa2, pa3, bf0, bf1);
                mma_f16(co[2 * ntp + 1][0], co[2 * ntp + 1][1], co[2 * ntp + 1][2], co[2 * ntp + 1][3],
                        pa0, pa1, pa2, pa3, bf2, bf3);
            }
        }

        sbuf = (sbuf + 1 == 3) ? 0 : sbuf + 1;
    }

    const float il = 1.0f / l_lo, ih = 1.0f / l_hi;
    __half* yb = y + ((size_t)b * S_LEN + q0 + w * 16 + (lane >> 2)) * D_MODEL + h * DH + 2 * jsel;
#pragma unroll
    for (int nt = 0; nt < 8; nt++) {
        *(uint32_t*)(yb + nt * 8)                       = pack_h2(co[nt][0] * il, co[nt][1] * il);
        *(uint32_t*)(yb + nt * 8 + 8 * (size_t)D_MODEL) = pack_h2(co[nt][2] * ih, co[nt][3] * ih);
    }
}

// ---------------------------------------------------------------------------
extern "C" void kernel_launch(void* const* d_in, const int* in_sizes, int n_in,
                              void* d_out, int out_size) {
    const float* x      = (const float*)d_in[0];
    const float* w_attn = (const float*)d_in[1];
    const float* w_proj = (const float*)d_in[2];
    float* out = (float*)d_out;

    __half *qkv, *yb, *xc, *wac, *wpc;
    cudaGetSymbolAddress((void**)&qkv, g_qkv);
    cudaGetSymbolAddress((void**)&yb, g_y);
    cudaGetSymbolAddress((void**)&xc, g_xc);
    cudaGetSymbolAddress((void**)&wac, g_wac);
    cudaGetSymbolAddress((void**)&wpc, g_wpc);

    cudaFuncSetAttribute(gemm_f16<true>,  cudaFuncAttributeMaxDynamicSharedMemorySize, GEMM_SMEM);
    cudaFuncSetAttribute(gemm_f16<false>, cudaFuncAttributeMaxDynamicSharedMemorySize, GEMM_SMEM);
    cudaFuncSetAttribute(attn_f16, cudaFuncAttributeMaxDynamicSharedMemorySize, ATT_SMEM);

    round_all<<<(RND_TOTAL + 255) / 256, 256>>>(x, w_attn, w_proj);

    dim3 g1(D3 / TBN, M_ROWS / TBM);
    gemm_f16<true><<<g1, 256, GEMM_SMEM>>>(xc, wac, qkv, M_ROWS, D3, D_MODEL);

    dim3 ga(S_LEN / 128, N_HEADS, BATCH);
    attn_f16<<<ga, 256, ATT_SMEM>>>(qkv, yb);

    dim3 g2(D_MODEL / TBN, M_ROWS / TBM);
    gemm_f16<false><<<g2, 256, GEMM_SMEM>>>(yb, wpc, out, M_ROWS, D_MODEL, D_MODEL);
}

// round 12
// speedup vs baseline: 1.2411x; 1.0562x over previous
#include <cuda_runtime.h>
#include <cuda_fp16.h>
#include <cstdint>
#include <cstddef>

// ---------------------------------------------------------------------------
// CausalSelfAttention: out = proj( causal_attn( x @ Wqkv^T ) )
// fp16 mma.sync m16n8k16. GEMM: 128x128 tile, K-stage 64 (128B rows), 3-stage
// cp.async ring, 2 CTA/SM. Attention: fp16 flash, f16x2 exp, ones-MMA row
// sums, 3-stage K/V pipeline. Fused pre-round kernel.
// ---------------------------------------------------------------------------

#define BATCH   4
#define S_LEN   2048
#define D_MODEL 1024
#define D3      3072
#define N_HEADS 16
#define DH      64
#define M_ROWS  (BATCH * S_LEN)   // 8192

__device__ __half g_qkv[(size_t)M_ROWS * D3];
__device__ __half g_y[(size_t)M_ROWS * D_MODEL];
__device__ __half g_xc[(size_t)M_ROWS * D_MODEL];
__device__ __half g_wac[(size_t)D3 * D_MODEL];
__device__ __half g_wpc[(size_t)D_MODEL * D_MODEL];

// ---- helpers ----------------------------------------------------------------
__device__ __forceinline__ uint32_t pack_h2(float a, float b) {
    __half2 h = __floats2half2_rn(a, b);
    return *(uint32_t*)&h;
}
__device__ __forceinline__ float ex2f(float x) {
    float r;
    asm("ex2.approx.ftz.f32 %0, %1;" : "=f"(r) : "f"(x));
    return r;
}
__device__ __forceinline__ uint32_t h2ex2(uint32_t x) {
    uint32_t r;
    asm("ex2.approx.f16x2 %0, %1;" : "=r"(r) : "r"(x));
    return r;
}
__device__ __forceinline__ void ldsm_x4(uint32_t addr, uint32_t& r0, uint32_t& r1,
                                        uint32_t& r2, uint32_t& r3) {
    asm volatile("ldmatrix.sync.aligned.m8n8.x4.shared.b16 {%0,%1,%2,%3}, [%4];"
                 : "=r"(r0), "=r"(r1), "=r"(r2), "=r"(r3) : "r"(addr));
}
__device__ __forceinline__ void ldsm_x4t(uint32_t addr, uint32_t& r0, uint32_t& r1,
                                         uint32_t& r2, uint32_t& r3) {
    asm volatile("ldmatrix.sync.aligned.m8n8.x4.trans.shared.b16 {%0,%1,%2,%3}, [%4];"
                 : "=r"(r0), "=r"(r1), "=r"(r2), "=r"(r3) : "r"(addr));
}
__device__ __forceinline__ void mma_f16(float& c0, float& c1, float& c2, float& c3,
                                        uint32_t a0, uint32_t a1, uint32_t a2, uint32_t a3,
                                        uint32_t b0, uint32_t b1) {
    asm volatile("mma.sync.aligned.m16n8k16.row.col.f32.f16.f16.f32 "
                 "{%0,%1,%2,%3}, {%4,%5,%6,%7}, {%8,%9}, {%0,%1,%2,%3};"
                 : "+f"(c0), "+f"(c1), "+f"(c2), "+f"(c3)
                 : "r"(a0), "r"(a1), "r"(a2), "r"(a3), "r"(b0), "r"(b1));
}
__device__ __forceinline__ void cp16(uint32_t dst, const void* src) {
    asm volatile("cp.async.cg.shared.global [%0], [%1], 16;" :: "r"(dst), "l"(src));
}
#define CP_COMMIT() asm volatile("cp.async.commit_group;")
#define CP_WAIT(n)  asm volatile("cp.async.wait_group %0;" :: "n"(n))

__device__ __forceinline__ uint32_t smem_u32(const void* p) {
    return (uint32_t)__cvta_generic_to_shared(p);
}

// ---------------------------------------------------------------------------
// Fused pre-round fp32 -> fp16 for x, w_attn, w_proj (one launch)
// ---------------------------------------------------------------------------
#define XC_N4  (M_ROWS * D_MODEL / 4)
#define WAC_N4 (D3 * D_MODEL / 4)
#define WPC_N4 (D_MODEL * D_MODEL / 4)
#define RND_TOTAL (XC_N4 + WAC_N4 + WPC_N4)

__global__ void round_all(const float* __restrict__ x, const float* __restrict__ wa,
                          const float* __restrict__ wp) {
    int i = blockIdx.x * blockDim.x + threadIdx.x;
    if (i >= RND_TOTAL) return;
    const float* src;
    __half* dst;
    int j;
    if (i < XC_N4)                { src = x;  dst = g_xc;  j = i; }
    else if (i < XC_N4 + WAC_N4)  { src = wa; dst = g_wac; j = i - XC_N4; }
    else                          { src = wp; dst = g_wpc; j = i - XC_N4 - WAC_N4; }
    float4 v = ((const float4*)src)[j];
    uint2 r = {pack_h2(v.x, v.y), pack_h2(v.z, v.w)};
    ((uint2*)dst)[j] = r;
}

// ---------------------------------------------------------------------------
// fp16 GEMM (NT): C[M,N] = A[M,K] @ B[N,K]^T
// Block 128x128, K-stage 64 halfs (128B rows, swizzle ch^(row&7)), 8 warps 2x4,
// warp 64x32. 3-stage ring, CP_WAIT(1) -> sync -> prefetch -> commit -> compute.
// ---------------------------------------------------------------------------
#define TBM 128
#define TBN 128
#define TBKH 64
#define GSTG 3
#define G_TILE_BYTES 16384                 // 128 rows x 128B
#define G_STAGE_BYTES (2 * G_TILE_BYTES)   // A + B = 32768
#define GEMM_SMEM (GSTG * G_STAGE_BYTES)   // 98304

template <bool HALF_OUT>
__global__ __launch_bounds__(256, 2)
void gemm_f16(const __half* __restrict__ A, const __half* __restrict__ B,
              void* __restrict__ Cv, int M, int N, int K) {
    extern __shared__ uint32_t sh[];

    const int tid    = threadIdx.x;
    const int lane   = tid & 31;
    const int warp   = tid >> 5;
    const int warp_m = warp >> 2;
    const int warp_n = warp & 3;
    const int row0   = blockIdx.y * TBM;
    const int col0   = blockIdx.x * TBN;

    const __half* Ab = A + (size_t)row0 * K;
    const __half* Bb = B + (size_t)col0 * K;

    const uint32_t base = smem_u32(sh);
    uint32_t sA[GSTG], sB[GSTG];
#pragma unroll
    for (int s = 0; s < GSTG; s++) { sA[s] = base + s * G_STAGE_BYTES; sB[s] = sA[s] + G_TILE_BYTES; }

    // cp.async mapping: 128 rows x 8 chunks(16B) = 1024 per tile; 4/thread each
    uint32_t l_rel[4], l_soff[4];
#pragma unroll
    for (int r = 0; r < 4; r++) {
        int idx = tid + 256 * r, row = idx >> 3, c = idx & 7;
        l_rel[r]  = (uint32_t)(row * 128 + ((c ^ (row & 7)) << 4));
        l_soff[r] = (uint32_t)(row * K + c * 8);
    }

    // ldsm row constants
    const int mat = lane >> 3, rr = lane & 7;
    uint32_t a_rowOff[4]; int a_rx[4];
#pragma unroll
    for (int mt = 0; mt < 4; mt++) {
        int row = warp_m * 64 + mt * 16 + ((mat & 1) << 3) + rr;
        a_rowOff[mt] = (uint32_t)(row * 128);
        a_rx[mt] = row & 7;
    }
    const int abit = mat >> 1;
    uint32_t b_rowOff[2]; int b_rx[2];
#pragma unroll
    for (int ntp = 0; ntp < 2; ntp++) {
        int row = warp_n * 32 + ntp * 16 + ((mat >> 1) << 3) + rr;
        b_rowOff[ntp] = (uint32_t)(row * 128);
        b_rx[ntp] = row & 7;
    }
    const int bbit = mat & 1;

    float c[4][4][4];
#pragma unroll
    for (int i = 0; i < 4; i++)
#pragma unroll
        for (int j = 0; j < 4; j++)
#pragma unroll
            for (int q = 0; q < 4; q++) c[i][j][q] = 0.f;

    const int NIT = K / TBKH;   // 16

    // prologue: stages 0,1
#pragma unroll
    for (int s = 0; s < 2; s++) {
#pragma unroll
        for (int r = 0; r < 4; r++) {
            cp16(sA[s] + l_rel[r], Ab + l_soff[r] + s * TBKH);
            cp16(sB[s] + l_rel[r], Bb + l_soff[r] + s * TBKH);
        }
        CP_COMMIT();
    }

    int buf = 0;
    for (int it = 0; it < NIT; it++) {
        CP_WAIT(1);        // stage `it` landed (FIFO; 2 groups pending at top)
        __syncthreads();   // visibility + readers of reused slot done

        if (it + 2 < NIT) {
            const int k0 = (it + 2) * TBKH;
            const int ns = (buf + 2 >= GSTG) ? (buf + 2 - GSTG) : (buf + 2);
#pragma unroll
            for (int r = 0; r < 4; r++) {
                cp16(sA[ns] + l_rel[r], Ab + l_soff[r] + k0);
                cp16(sB[ns] + l_rel[r], Bb + l_soff[r] + k0);
            }
        }
        CP_COMMIT();

#pragma unroll
        for (int ks = 0; ks < 4; ks++) {
            uint32_t af[4][4];
#pragma unroll
            for (int mt = 0; mt < 4; mt++) {
                int ch = ks * 2 + abit;
                ldsm_x4(sA[buf] + a_rowOff[mt] + ((ch ^ a_rx[mt]) << 4),
                        af[mt][0], af[mt][1], af[mt][2], af[mt][3]);
            }
            uint32_t bf[2][4];
#pragma unroll
            for (int ntp = 0; ntp < 2; ntp++) {
                int ch = ks * 2 + bbit;
                ldsm_x4(sB[buf] + b_rowOff[ntp] + ((ch ^ b_rx[ntp]) << 4),
                        bf[ntp][0], bf[ntp][1], bf[ntp][2], bf[ntp][3]);
            }
#pragma unroll
            for (int mt = 0; mt < 4; mt++)
#pragma unroll
                for (int nt = 0; nt < 4; nt++) {
                    const uint32_t* bp = &bf[nt >> 1][(nt & 1) * 2];
                    mma_f16(c[mt][nt][0], c[mt][nt][1], c[mt][nt][2], c[mt][nt][3],
                            af[mt][0], af[mt][1], af[mt][2], af[mt][3], bp[0], bp[1]);
                }
        }
        buf = (buf + 1 == GSTG) ? 0 : buf + 1;
    }

    const int rql = lane >> 2;
    const int cpl = (lane & 3) * 2;
#pragma unroll
    for (int mt = 0; mt < 4; mt++) {
        int rg = row0 + warp_m * 64 + mt * 16 + rql;
#pragma unroll
        for (int nt = 0; nt < 4; nt++) {
            int cg = col0 + warp_n * 32 + nt * 8 + cpl;
            if (HALF_OUT) {
                __half* C = (__half*)Cv;
                *(uint32_t*)(C + (size_t)rg * N + cg)       = pack_h2(c[mt][nt][0], c[mt][nt][1]);
                *(uint32_t*)(C + (size_t)(rg + 8) * N + cg) = pack_h2(c[mt][nt][2], c[mt][nt][3]);
            } else {
                float* C = (float*)Cv;
                float2 v0 = {c[mt][nt][0], c[mt][nt][1]};
                float2 v1 = {c[mt][nt][2], c[mt][nt][3]};
                *(float2*)(C + (size_t)rg * N + cg)       = v0;
                *(float2*)(C + (size_t)(rg + 8) * N + cg) = v1;
            }
        }
    }
}

// ---------------------------------------------------------------------------
// fp16 causal flash attention: f16x2 exp + ones-MMA row sums, 3-stage K/V ring.
// (unchanged from R11 — passing at 346.9)
// ---------------------------------------------------------------------------
#define ATT_SCALE 0.18033688f
#define ATT_SMEM  65536
#define ONES_H2   0x3C003C00u

__global__ __launch_bounds__(256, 2)
void attn_f16(const __half* __restrict__ qkv, __half* __restrict__ y) {
    extern __shared__ uint32_t smu[];
    char* smc = (char*)smu;
    const uint32_t qs_base = smem_u32(smu);
    const uint32_t ks_base = qs_base + 16384;
    const uint32_t vs_base = ks_base + 3 * 8192;

    const int tid  = threadIdx.x;
    const int lane = tid & 31;
    const int w    = tid >> 5;
    const int qi   = (S_LEN / 128 - 1) - blockIdx.x;
    const int h    = blockIdx.y;
    const int b    = blockIdx.z;
    const int q0   = qi * 128;

    const __half* qb = qkv + (size_t)b * S_LEN * D3 + h * DH;
    const __half* kb = qb + D_MODEL;
    const __half* vb = qb + 2 * D_MODEL;

    int l_row[2], l_chk[2];
    uint32_t l_rel[2];
#pragma unroll
    for (int r = 0; r < 2; r++) {
        int idx = tid + 256 * r;
        l_row[r] = idx >> 3; l_chk[r] = idx & 7;
        l_rel[r] = (uint32_t)(l_row[r] * 128 + ((l_chk[r] ^ (l_row[r] & 7)) << 4));
    }

    const int njb = 2 * qi + 2;

    // prologue: issue K/V tiles 0 and 1
#pragma unroll
    for (int s = 0; s < 2; s++) {
        const int kn = s * 64;
        const uint32_t kd = ks_base + s * 8192;
        const uint32_t vd = vs_base + s * 8192;
#pragma unroll
        for (int r = 0; r < 2; r++) {
            cp16(kd + l_rel[r], kb + (size_t)(kn + l_row[r]) * D3 + l_chk[r] * 8);
            cp16(vd + l_rel[r], vb + (size_t)(kn + l_row[r]) * D3 + l_chk[r] * 8);
        }
        CP_COMMIT();
    }

    // load Q (scale, fp16) into smem
#pragma unroll
    for (int r = 0; r < 4; r++) {
        int idx = tid + 256 * r, row = idx >> 3, ch = idx & 7;
        uint4 raw = *(const uint4*)(qb + (size_t)(q0 + row) * D3 + ch * 8);
        uint32_t* rp = (uint32_t*)&raw;
        uint4 outv;
        uint32_t* op = (uint32_t*)&outv;
#pragma unroll
        for (int j = 0; j < 4; j++) {
            __half2 hv = *(__half2*)&rp[j];
            float2 f = __half22float2(hv);
            op[j] = pack_h2(f.x * ATT_SCALE, f.y * ATT_SCALE);
        }
        *(uint4*)(smc + row * 128 + ((ch ^ (row & 7)) << 4)) = outv;
    }
    __syncthreads();

    const int mat = lane >> 3, rr = lane & 7;
    uint32_t qf[4][4];
    {
        int rowA = w * 16 + ((mat & 1) << 3) + rr;
        int rbase = rowA * 128;
        int rx = rowA & 7;
#pragma unroll
        for (int ks = 0; ks < 4; ks++) {
            int ch = ks * 2 + (mat >> 1);
            ldsm_x4(qs_base + rbase + ((ch ^ rx) << 4), qf[ks][0], qf[ks][1], qf[ks][2], qf[ks][3]);
        }
    }
    uint32_t krowOff[4]; int krx[4];
#pragma unroll
    for (int ntp = 0; ntp < 4; ntp++) {
        int rowB = ntp * 16 + ((mat >> 1) << 3) + rr;
        krowOff[ntp] = (uint32_t)(rowB * 128);
        krx[ntp] = rowB & 7;
    }
    const int kbit = mat & 1;
    uint32_t vrowOff[4]; int vrx[4];
#pragma unroll
    for (int kt = 0; kt < 4; kt++) {
        int rowV = kt * 16 + ((mat & 1) << 3) + rr;
        vrowOff[kt] = (uint32_t)(rowV * 128);
        vrx[kt] = rowV & 7;
    }
    const int vbit = mat >> 1;

    float m_lo = -1e30f, m_hi = -1e30f, l_lo = 0.f, l_hi = 0.f;
    float co[8][4];
#pragma unroll
    for (int i = 0; i < 8; i++)
#pragma unroll
        for (int q = 0; q < 4; q++) co[i][q] = 0.f;

    const int rlo  = q0 + w * 16 + (lane >> 2);
    const int jsel = lane & 3;

    int sbuf = 0;

    for (int jb = 0; jb < njb; jb++) {
        CP_WAIT(1);
        __syncthreads();

        if (jb + 2 < njb) {
            const int kn = (jb + 2) * 64;
            const int ns = (sbuf + 2 >= 3) ? (sbuf - 1) : (sbuf + 2);
            const uint32_t kd = ks_base + ns * 8192;
            const uint32_t vd = vs_base + ns * 8192;
#pragma unroll
            for (int r = 0; r < 2; r++) {
                cp16(kd + l_rel[r], kb + (size_t)(kn + l_row[r]) * D3 + l_chk[r] * 8);
                cp16(vd + l_rel[r], vb + (size_t)(kn + l_row[r]) * D3 + l_chk[r] * 8);
            }
        }
        CP_COMMIT();

        const uint32_t kbuf = ks_base + (uint32_t)(sbuf * 8192);
        const uint32_t vbuf = vs_base + (uint32_t)(sbuf * 8192);

        float cs[8][4];
#pragma unroll
        for (int i = 0; i < 8; i++)
#pragma unroll
            for (int q = 0; q < 4; q++) cs[i][q] = 0.f;

#pragma unroll
        for (int ks = 0; ks < 4; ks++) {
            uint32_t bf[4][4];
            int ch = ks * 2 + kbit;
#pragma unroll
            for (int ntp = 0; ntp < 4; ntp++)
                ldsm_x4(kbuf + krowOff[ntp] + ((ch ^ krx[ntp]) << 4),
                        bf[ntp][0], bf[ntp][1], bf[ntp][2], bf[ntp][3]);
#pragma unroll
            for (int nt = 0; nt < 8; nt++) {
                const uint32_t* bp = &bf[nt >> 1][(nt & 1) * 2];
                mma_f16(cs[nt][0], cs[nt][1], cs[nt][2], cs[nt][3],
                        qf[ks][0], qf[ks][1], qf[ks][2], qf[ks][3], bp[0], bp[1]);
            }
        }

        if (jb * 64 >= q0) {
#pragma unroll
            for (int nt = 0; nt < 8; nt++) {
                int cb = jb * 64 + nt * 8 + 2 * jsel;
                if (cb     > rlo)     cs[nt][0] = -1e30f;
                if (cb + 1 > rlo)     cs[nt][1] = -1e30f;
                if (cb     > rlo + 8) cs[nt][2] = -1e30f;
                if (cb + 1 > rlo + 8) cs[nt][3] = -1e30f;
            }
        }

        float ml = -1e30f, mh = -1e30f;
#pragma unroll
        for (int nt = 0; nt < 8; nt++) {
            ml = fmaxf(ml, fmaxf(cs[nt][0], cs[nt][1]));
            mh = fmaxf(mh, fmaxf(cs[nt][2], cs[nt][3]));
        }
        ml = fmaxf(ml, __shfl_xor_sync(0xffffffffu, ml, 1));
        ml = fmaxf(ml, __shfl_xor_sync(0xffffffffu, ml, 2));
        mh = fmaxf(mh, __shfl_xor_sync(0xffffffffu, mh, 1));
        mh = fmaxf(mh, __shfl_xor_sync(0xffffffffu, mh, 2));
        float Ml = fmaxf(m_lo, ml), Mh = fmaxf(m_hi, mh);
        float al = ex2f(m_lo - Ml), ah = ex2f(m_hi - Mh);
        m_lo = Ml; m_hi = Mh;

        uint32_t pp[8][2];
#pragma unroll
        for (int nt = 0; nt < 8; nt++) {
            pp[nt][0] = h2ex2(pack_h2(cs[nt][0] - Ml, cs[nt][1] - Ml));
            pp[nt][1] = h2ex2(pack_h2(cs[nt][2] - Mh, cs[nt][3] - Mh));
        }

        float csum0 = 0.f, csum1 = 0.f, csum2 = 0.f, csum3 = 0.f;
#pragma unroll
        for (int kt = 0; kt < 4; kt++)
            mma_f16(csum0, csum1, csum2, csum3,
                    pp[2 * kt][0], pp[2 * kt][1], pp[2 * kt + 1][0], pp[2 * kt + 1][1],
                    ONES_H2, ONES_H2);
        l_lo = l_lo * al + csum0;
        l_hi = l_hi * ah + csum2;

#pragma unroll
        for (int i = 0; i < 8; i++) {
            co[i][0] *= al; co[i][1] *= al; co[i][2] *= ah; co[i][3] *= ah;
        }

#pragma unroll
        for (int kt = 0; kt < 4; kt++) {
            uint32_t pa0 = pp[2 * kt][0];
            uint32_t pa1 = pp[2 * kt][1];
            uint32_t pa2 = pp[2 * kt + 1][0];
            uint32_t pa3 = pp[2 * kt + 1][1];

#pragma unroll
            for (int ntp = 0; ntp < 4; ntp++) {
                uint32_t bf0, bf1, bf2, bf3;
                int ch = ntp * 2 + vbit;
                ldsm_x4t(vbuf + vrowOff[kt] + ((ch ^ vrx[kt]) << 4), bf0, bf1, bf2, bf3);
                mma_f16(co[2 * ntp][0], co[2 * ntp][1], co[2 * ntp][2], co[2 * ntp][3],
                        pa0, pa1, pa2, pa3, bf0, bf1);
                mma_f16(co[2 * ntp + 1][0], co[2 * ntp + 1][1], co[2 * ntp + 1][2], co[2 * ntp + 1][3],
                        pa0, pa1, pa2, pa3, bf2, bf3);
            }
        }

        sbuf = (sbuf + 1 == 3) ? 0 : sbuf + 1;
    }

    const float il = 1.0f / l_lo, ih = 1.0f / l_hi;
    __half* yb = y + ((size_t)b * S_LEN + q0 + w * 16 + (lane >> 2)) * D_MODEL + h * DH + 2 * jsel;
#pragma unroll
    for (int nt = 0; nt < 8; nt++) {
        *(uint32_t*)(yb + nt * 8)                       = pack_h2(co[nt][0] * il, co[nt][1] * il);
        *(uint32_t*)(yb + nt * 8 + 8 * (size_t)D_MODEL) = pack_h2(co[nt][2] * ih, co[nt][3] * ih);
    }
}

// ---------------------------------------------------------------------------
extern "C" void kernel_launch(void* const* d_in, const int* in_sizes, int n_in,
                              void* d_out, int out_size) {
    const float* x      = (const float*)d_in[0];
    const float* w_attn = (const float*)d_in[1];
    const float* w_proj = (const float*)d_in[2];
    float* out = (float*)d_out;

    __half *qkv, *yb, *xc, *wac, *wpc;
    cudaGetSymbolAddress((void**)&qkv, g_qkv);
    cudaGetSymbolAddress((void**)&yb, g_y);
    cudaGetSymbolAddress((void**)&xc, g_xc);
    cudaGetSymbolAddress((void**)&wac, g_wac);
    cudaGetSymbolAddress((void**)&wpc, g_wpc);

    cudaFuncSetAttribute(gemm_f16<true>,  cudaFuncAttributeMaxDynamicSharedMemorySize, GEMM_SMEM);
    cudaFuncSetAttribute(gemm_f16<false>, cudaFuncAttributeMaxDynamicSharedMemorySize, GEMM_SMEM);
    cudaFuncSetAttribute(attn_f16, cudaFuncAttributeMaxDynamicSharedMemorySize, ATT_SMEM);

    round_all<<<(RND_TOTAL + 255) / 256, 256>>>(x, w_attn, w_proj);

    dim3 g1(D3 / TBN, M_ROWS / TBM);
    gemm_f16<true><<<g1, 256, GEMM_SMEM>>>(xc, wac, qkv, M_ROWS, D3, D_MODEL);

    dim3 ga(S_LEN / 128, N_HEADS, BATCH);
    attn_f16<<<ga, 256, ATT_SMEM>>>(qkv, yb);

    dim3 g2(D_MODEL / TBN, M_ROWS / TBM);
    gemm_f16<false><<<g2, 256, GEMM_SMEM>>>(yb, wpc, out, M_ROWS, D_MODEL, D_MODEL);
}

// round 13
// speedup vs baseline: 1.2635x; 1.0181x over previous
#include <cuda_runtime.h>
#include <cuda_fp16.h>
#include <cstdint>
#include <cstddef>

// ---------------------------------------------------------------------------
// CausalSelfAttention: out = proj( causal_attn( x @ Wqkv^T ) )
// fp16 mma.sync m16n8k16. GEMM: 128x128 tile, K-stage 64, 3-stage ring,
// 2 CTA/SM. Attention: fp16 flash, 128-kv stages (two 64-col softmax passes),
// f16x2 exp, ones-MMA row sums, 3-stage pipeline. Fused pre-round kernel.
// ---------------------------------------------------------------------------

#define BATCH   4
#define S_LEN   2048
#define D_MODEL 1024
#define D3      3072
#define N_HEADS 16
#define DH      64
#define M_ROWS  (BATCH * S_LEN)   // 8192

__device__ __half g_qkv[(size_t)M_ROWS * D3];
__device__ __half g_y[(size_t)M_ROWS * D_MODEL];
__device__ __half g_xc[(size_t)M_ROWS * D_MODEL];
__device__ __half g_wac[(size_t)D3 * D_MODEL];
__device__ __half g_wpc[(size_t)D_MODEL * D_MODEL];

// ---- helpers ----------------------------------------------------------------
__device__ __forceinline__ uint32_t pack_h2(float a, float b) {
    __half2 h = __floats2half2_rn(a, b);
    return *(uint32_t*)&h;
}
__device__ __forceinline__ float ex2f(float x) {
    float r;
    asm("ex2.approx.ftz.f32 %0, %1;" : "=f"(r) : "f"(x));
    return r;
}
__device__ __forceinline__ uint32_t h2ex2(uint32_t x) {
    uint32_t r;
    asm("ex2.approx.f16x2 %0, %1;" : "=r"(r) : "r"(x));
    return r;
}
__device__ __forceinline__ void ldsm_x4(uint32_t addr, uint32_t& r0, uint32_t& r1,
                                        uint32_t& r2, uint32_t& r3) {
    asm volatile("ldmatrix.sync.aligned.m8n8.x4.shared.b16 {%0,%1,%2,%3}, [%4];"
                 : "=r"(r0), "=r"(r1), "=r"(r2), "=r"(r3) : "r"(addr));
}
__device__ __forceinline__ void ldsm_x4t(uint32_t addr, uint32_t& r0, uint32_t& r1,
                                         uint32_t& r2, uint32_t& r3) {
    asm volatile("ldmatrix.sync.aligned.m8n8.x4.trans.shared.b16 {%0,%1,%2,%3}, [%4];"
                 : "=r"(r0), "=r"(r1), "=r"(r2), "=r"(r3) : "r"(addr));
}
__device__ __forceinline__ void mma_f16(float& c0, float& c1, float& c2, float& c3,
                                        uint32_t a0, uint32_t a1, uint32_t a2, uint32_t a3,
                                        uint32_t b0, uint32_t b1) {
    asm volatile("mma.sync.aligned.m16n8k16.row.col.f32.f16.f16.f32 "
                 "{%0,%1,%2,%3}, {%4,%5,%6,%7}, {%8,%9}, {%0,%1,%2,%3};"
                 : "+f"(c0), "+f"(c1), "+f"(c2), "+f"(c3)
                 : "r"(a0), "r"(a1), "r"(a2), "r"(a3), "r"(b0), "r"(b1));
}
__device__ __forceinline__ void cp16(uint32_t dst, const void* src) {
    asm volatile("cp.async.cg.shared.global [%0], [%1], 16;" :: "r"(dst), "l"(src));
}
#define CP_COMMIT() asm volatile("cp.async.commit_group;")
#define CP_WAIT(n)  asm volatile("cp.async.wait_group %0;" :: "n"(n))

__device__ __forceinline__ uint32_t smem_u32(const void* p) {
    return (uint32_t)__cvta_generic_to_shared(p);
}

// ---------------------------------------------------------------------------
// Fused pre-round fp32 -> fp16 for x, w_attn, w_proj (one launch)
// ---------------------------------------------------------------------------
#define XC_N4  (M_ROWS * D_MODEL / 4)
#define WAC_N4 (D3 * D_MODEL / 4)
#define WPC_N4 (D_MODEL * D_MODEL / 4)
#define RND_TOTAL (XC_N4 + WAC_N4 + WPC_N4)

__global__ void round_all(const float* __restrict__ x, const float* __restrict__ wa,
                          const float* __restrict__ wp) {
    int i = blockIdx.x * blockDim.x + threadIdx.x;
    if (i >= RND_TOTAL) return;
    const float* src;
    __half* dst;
    int j;
    if (i < XC_N4)                { src = x;  dst = g_xc;  j = i; }
    else if (i < XC_N4 + WAC_N4)  { src = wa; dst = g_wac; j = i - XC_N4; }
    else                          { src = wp; dst = g_wpc; j = i - XC_N4 - WAC_N4; }
    float4 v = ((const float4*)src)[j];
    uint2 r = {pack_h2(v.x, v.y), pack_h2(v.z, v.w)};
    ((uint2*)dst)[j] = r;
}

// ---------------------------------------------------------------------------
// fp16 GEMM (NT): unchanged from R12 (passing, 2 CTA/SM, TBKH=64, 3 stages)
// ---------------------------------------------------------------------------
#define TBM 128
#define TBN 128
#define TBKH 64
#define GSTG 3
#define G_TILE_BYTES 16384
#define G_STAGE_BYTES (2 * G_TILE_BYTES)
#define GEMM_SMEM (GSTG * G_STAGE_BYTES)   // 98304

template <bool HALF_OUT>
__global__ __launch_bounds__(256, 2)
void gemm_f16(const __half* __restrict__ A, const __half* __restrict__ B,
              void* __restrict__ Cv, int M, int N, int K) {
    extern __shared__ uint32_t sh[];

    const int tid    = threadIdx.x;
    const int lane   = tid & 31;
    const int warp   = tid >> 5;
    const int warp_m = warp >> 2;
    const int warp_n = warp & 3;
    const int row0   = blockIdx.y * TBM;
    const int col0   = blockIdx.x * TBN;

    const __half* Ab = A + (size_t)row0 * K;
    const __half* Bb = B + (size_t)col0 * K;

    const uint32_t base = smem_u32(sh);
    uint32_t sA[GSTG], sB[GSTG];
#pragma unroll
    for (int s = 0; s < GSTG; s++) { sA[s] = base + s * G_STAGE_BYTES; sB[s] = sA[s] + G_TILE_BYTES; }

    uint32_t l_rel[4], l_soff[4];
#pragma unroll
    for (int r = 0; r < 4; r++) {
        int idx = tid + 256 * r, row = idx >> 3, c = idx & 7;
        l_rel[r]  = (uint32_t)(row * 128 + ((c ^ (row & 7)) << 4));
        l_soff[r] = (uint32_t)(row * K + c * 8);
    }

    const int mat = lane >> 3, rr = lane & 7;
    uint32_t a_rowOff[4]; int a_rx[4];
#pragma unroll
    for (int mt = 0; mt < 4; mt++) {
        int row = warp_m * 64 + mt * 16 + ((mat & 1) << 3) + rr;
        a_rowOff[mt] = (uint32_t)(row * 128);
        a_rx[mt] = row & 7;
    }
    const int abit = mat >> 1;
    uint32_t b_rowOff[2]; int b_rx[2];
#pragma unroll
    for (int ntp = 0; ntp < 2; ntp++) {
        int row = warp_n * 32 + ntp * 16 + ((mat >> 1) << 3) + rr;
        b_rowOff[ntp] = (uint32_t)(row * 128);
        b_rx[ntp] = row & 7;
    }
    const int bbit = mat & 1;

    float c[4][4][4];
#pragma unroll
    for (int i = 0; i < 4; i++)
#pragma unroll
        for (int j = 0; j < 4; j++)
#pragma unroll
            for (int q = 0; q < 4; q++) c[i][j][q] = 0.f;

    const int NIT = K / TBKH;   // 16

#pragma unroll
    for (int s = 0; s < 2; s++) {
#pragma unroll
        for (int r = 0; r < 4; r++) {
            cp16(sA[s] + l_rel[r], Ab + l_soff[r] + s * TBKH);
            cp16(sB[s] + l_rel[r], Bb + l_soff[r] + s * TBKH);
        }
        CP_COMMIT();
    }

    int buf = 0;
    for (int it = 0; it < NIT; it++) {
        CP_WAIT(1);
        __syncthreads();

        if (it + 2 < NIT) {
            const int k0 = (it + 2) * TBKH;
            const int ns = (buf + 2 >= GSTG) ? (buf + 2 - GSTG) : (buf + 2);
#pragma unroll
            for (int r = 0; r < 4; r++) {
                cp16(sA[ns] + l_rel[r], Ab + l_soff[r] + k0);
                cp16(sB[ns] + l_rel[r], Bb + l_soff[r] + k0);
            }
        }
        CP_COMMIT();

#pragma unroll
        for (int ks = 0; ks < 4; ks++) {
            uint32_t af[4][4];
#pragma unroll
            for (int mt = 0; mt < 4; mt++) {
                int ch = ks * 2 + abit;
                ldsm_x4(sA[buf] + a_rowOff[mt] + ((ch ^ a_rx[mt]) << 4),
                        af[mt][0], af[mt][1], af[mt][2], af[mt][3]);
            }
            uint32_t bf[2][4];
#pragma unroll
            for (int ntp = 0; ntp < 2; ntp++) {
                int ch = ks * 2 + bbit;
                ldsm_x4(sB[buf] + b_rowOff[ntp] + ((ch ^ b_rx[ntp]) << 4),
                        bf[ntp][0], bf[ntp][1], bf[ntp][2], bf[ntp][3]);
            }
#pragma unroll
            for (int mt = 0; mt < 4; mt++)
#pragma unroll
                for (int nt = 0; nt < 4; nt++) {
                    const uint32_t* bp = &bf[nt >> 1][(nt & 1) * 2];
                    mma_f16(c[mt][nt][0], c[mt][nt][1], c[mt][nt][2], c[mt][nt][3],
                            af[mt][0], af[mt][1], af[mt][2], af[mt][3], bp[0], bp[1]);
                }
        }
        buf = (buf + 1 == GSTG) ? 0 : buf + 1;
    }

    const int rql = lane >> 2;
    const int cpl = (lane & 3) * 2;
#pragma unroll
    for (int mt = 0; mt < 4; mt++) {
        int rg = row0 + warp_m * 64 + mt * 16 + rql;
#pragma unroll
        for (int nt = 0; nt < 4; nt++) {
            int cg = col0 + warp_n * 32 + nt * 8 + cpl;
            if (HALF_OUT) {
                __half* C = (__half*)Cv;
                *(uint32_t*)(C + (size_t)rg * N + cg)       = pack_h2(c[mt][nt][0], c[mt][nt][1]);
                *(uint32_t*)(C + (size_t)(rg + 8) * N + cg) = pack_h2(c[mt][nt][2], c[mt][nt][3]);
            } else {
                float* C = (float*)Cv;
                float2 v0 = {c[mt][nt][0], c[mt][nt][1]};
                float2 v1 = {c[mt][nt][2], c[mt][nt][3]};
                *(float2*)(C + (size_t)rg * N + cg)       = v0;
                *(float2*)(C + (size_t)(rg + 8) * N + cg) = v1;
            }
        }
    }
}

// ---------------------------------------------------------------------------
// fp16 causal flash attention: 128-kv pipeline stages, two 64-col softmax
// passes per stage. 3-stage ring. SMEM: Q 16K + 3x(K 16K + V 16K) = 112KB.
// ---------------------------------------------------------------------------
#define ATT_SCALE 0.18033688f
#define ATT_STAGE_BYTES 32768
#define ATT_SMEM  (16384 + 3 * ATT_STAGE_BYTES)   // 114688
#define ONES_H2   0x3C003C00u

__global__ __launch_bounds__(256, 2)
void attn_f16(const __half* __restrict__ qkv, __half* __restrict__ y) {
    extern __shared__ uint32_t smu[];
    char* smc = (char*)smu;
    const uint32_t qs_base = smem_u32(smu);
    const uint32_t st_base = qs_base + 16384;   // stage s: K at +s*32768, V at +16384

    const int tid  = threadIdx.x;
    const int lane = tid & 31;
    const int w    = tid >> 5;
    const int qi   = (S_LEN / 128 - 1) - blockIdx.x;
    const int h    = blockIdx.y;
    const int b    = blockIdx.z;
    const int q0   = qi * 128;

    const __half* qb = qkv + (size_t)b * S_LEN * D3 + h * DH;
    const __half* kb = qb + D_MODEL;
    const __half* vb = qb + 2 * D_MODEL;

    // K/V cp.async mapping: 128 rows x 8 chunks = 1024 per tile; 4/thread
    int l_row[4], l_chk[4];
    uint32_t l_rel[4];
#pragma unroll
    for (int r = 0; r < 4; r++) {
        int idx = tid + 256 * r;
        l_row[r] = idx >> 3; l_chk[r] = idx & 7;
        l_rel[r] = (uint32_t)(l_row[r] * 128 + ((l_chk[r] ^ (l_row[r] & 7)) << 4));
    }

    const int njb = qi + 1;   // 128-kv tiles

    // prologue: issue tile 0; tile 1 (or empty commit to keep 2 groups pending)
    {
        const uint32_t kd = st_base, vd = st_base + 16384;
#pragma unroll
        for (int r = 0; r < 4; r++) {
            cp16(kd + l_rel[r], kb + (size_t)l_row[r] * D3 + l_chk[r] * 8);
            cp16(vd + l_rel[r], vb + (size_t)l_row[r] * D3 + l_chk[r] * 8);
        }
        CP_COMMIT();
    }
    if (njb > 1) {
        const uint32_t kd = st_base + ATT_STAGE_BYTES, vd = kd + 16384;
#pragma unroll
        for (int r = 0; r < 4; r++) {
            cp16(kd + l_rel[r], kb + (size_t)(128 + l_row[r]) * D3 + l_chk[r] * 8);
            cp16(vd + l_rel[r], vb + (size_t)(128 + l_row[r]) * D3 + l_chk[r] * 8);
        }
    }
    CP_COMMIT();

    // load Q (scale, fp16) into smem
#pragma unroll
    for (int r = 0; r < 4; r++) {
        int idx = tid + 256 * r, row = idx >> 3, ch = idx & 7;
        uint4 raw = *(const uint4*)(qb + (size_t)(q0 + row) * D3 + ch * 8);
        uint32_t* rp = (uint32_t*)&raw;
        uint4 outv;
        uint32_t* op = (uint32_t*)&outv;
#pragma unroll
        for (int j = 0; j < 4; j++) {
            __half2 hv = *(__half2*)&rp[j];
            float2 f = __half22float2(hv);
            op[j] = pack_h2(f.x * ATT_SCALE, f.y * ATT_SCALE);
        }
        *(uint4*)(smc + row * 128 + ((ch ^ (row & 7)) << 4)) = outv;
    }
    __syncthreads();

    const int mat = lane >> 3, rr = lane & 7;
    uint32_t qf[4][4];
    {
        int rowA = w * 16 + ((mat & 1) << 3) + rr;
        int rbase = rowA * 128;
        int rx = rowA & 7;
#pragma unroll
        for (int ks = 0; ks < 4; ks++) {
            int ch = ks * 2 + (mat >> 1);
            ldsm_x4(qs_base + rbase + ((ch ^ rx) << 4), qf[ks][0], qf[ks][1], qf[ks][2], qf[ks][3]);
        }
    }
    uint32_t krowOff[4]; int krx[4];
#pragma unroll
    for (int ntp = 0; ntp < 4; ntp++) {
        int rowB = ntp * 16 + ((mat >> 1) << 3) + rr;
        krowOff[ntp] = (uint32_t)(rowB * 128);
        krx[ntp] = rowB & 7;
    }
    const int kbit = mat & 1;
    uint32_t vrowOff[4]; int vrx[4];
#pragma unroll
    for (int kt = 0; kt < 4; kt++) {
        int rowV = kt * 16 + ((mat & 1) << 3) + rr;
        vrowOff[kt] = (uint32_t)(rowV * 128);
        vrx[kt] = rowV & 7;
    }
    const int vbit = mat >> 1;

    float m_lo = -1e30f, m_hi = -1e30f, l_lo = 0.f, l_hi = 0.f;
    float co[8][4];
#pragma unroll
    for (int i = 0; i < 8; i++)
#pragma unroll
        for (int q = 0; q < 4; q++) co[i][q] = 0.f;

    const int rlo  = q0 + w * 16 + (lane >> 2);
    const int jsel = lane & 3;

    int sbuf = 0;

    for (int jb = 0; jb < njb; jb++) {
        CP_WAIT(1);        // tile jb landed (FIFO; 2 groups pending at loop top)
        __syncthreads();   // visibility + readers of reused slot done

        if (jb + 2 < njb) {
            const int kn = (jb + 2) * 128;
            const int ns = (sbuf + 2 >= 3) ? (sbuf - 1) : (sbuf + 2);
            const uint32_t kd = st_base + ns * ATT_STAGE_BYTES, vd = kd + 16384;
#pragma unroll
            for (int r = 0; r < 4; r++) {
                cp16(kd + l_rel[r], kb + (size_t)(kn + l_row[r]) * D3 + l_chk[r] * 8);
                cp16(vd + l_rel[r], vb + (size_t)(kn + l_row[r]) * D3 + l_chk[r] * 8);
            }
        }
        CP_COMMIT();

        const uint32_t stg = st_base + (uint32_t)(sbuf * ATT_STAGE_BYTES);

        // two 64-col passes over the 128-kv stage
#pragma unroll
        for (int hh = 0; hh < 2; hh++) {
            const uint32_t kbuf = stg + hh * 8192;           // rows 64*hh..
            const uint32_t vbuf = stg + 16384 + hh * 8192;
            const int cbase = jb * 128 + hh * 64;

            // ---- S = Q @ K^T ----
            float cs[8][4];
#pragma unroll
            for (int i = 0; i < 8; i++)
#pragma unroll
                for (int q = 0; q < 4; q++) cs[i][q] = 0.f;

#pragma unroll
            for (int ks = 0; ks < 4; ks++) {
                uint32_t bf[4][4];
                int ch = ks * 2 + kbit;
#pragma unroll
                for (int ntp = 0; ntp < 4; ntp++)
                    ldsm_x4(kbuf + krowOff[ntp] + ((ch ^ krx[ntp]) << 4),
                            bf[ntp][0], bf[ntp][1], bf[ntp][2], bf[ntp][3]);
#pragma unroll
                for (int nt = 0; nt < 8; nt++) {
                    const uint32_t* bp = &bf[nt >> 1][(nt & 1) * 2];
                    mma_f16(cs[nt][0], cs[nt][1], cs[nt][2], cs[nt][3],
                            qf[ks][0], qf[ks][1], qf[ks][2], qf[ks][3], bp[0], bp[1]);
                }
            }

            // ---- causal mask (final tile halves only) ----
            if (cbase >= q0) {
#pragma unroll
                for (int nt = 0; nt < 8; nt++) {
                    int cb = cbase + nt * 8 + 2 * jsel;
                    if (cb     > rlo)     cs[nt][0] = -1e30f;
                    if (cb + 1 > rlo)     cs[nt][1] = -1e30f;
                    if (cb     > rlo + 8) cs[nt][2] = -1e30f;
                    if (cb + 1 > rlo + 8) cs[nt][3] = -1e30f;
                }
            }

            // ---- online softmax (base-2); P in fp16x2 ----
            float ml = -1e30f, mh = -1e30f;
#pragma unroll
            for (int nt = 0; nt < 8; nt++) {
                ml = fmaxf(ml, fmaxf(cs[nt][0], cs[nt][1]));
                mh = fmaxf(mh, fmaxf(cs[nt][2], cs[nt][3]));
            }
            ml = fmaxf(ml, __shfl_xor_sync(0xffffffffu, ml, 1));
            ml = fmaxf(ml, __shfl_xor_sync(0xffffffffu, ml, 2));
            mh = fmaxf(mh, __shfl_xor_sync(0xffffffffu, mh, 1));
            mh = fmaxf(mh, __shfl_xor_sync(0xffffffffu, mh, 2));
            float Ml = fmaxf(m_lo, ml), Mh = fmaxf(m_hi, mh);
            float al = ex2f(m_lo - Ml), ah = ex2f(m_hi - Mh);
            m_lo = Ml; m_hi = Mh;

            uint32_t pp[8][2];
#pragma unroll
            for (int nt = 0; nt < 8; nt++) {
                pp[nt][0] = h2ex2(pack_h2(cs[nt][0] - Ml, cs[nt][1] - Ml));
                pp[nt][1] = h2ex2(pack_h2(cs[nt][2] - Mh, cs[nt][3] - Mh));
            }

            float csum0 = 0.f, csum1 = 0.f, csum2 = 0.f, csum3 = 0.f;
#pragma unroll
            for (int kt = 0; kt < 4; kt++)
                mma_f16(csum0, csum1, csum2, csum3,
                        pp[2 * kt][0], pp[2 * kt][1], pp[2 * kt + 1][0], pp[2 * kt + 1][1],
                        ONES_H2, ONES_H2);
            l_lo = l_lo * al + csum0;
            l_hi = l_hi * ah + csum2;

#pragma unroll
            for (int i = 0; i < 8; i++) {
                co[i][0] *= al; co[i][1] *= al; co[i][2] *= ah; co[i][3] *= ah;
            }

            // ---- O += P @ V ----
#pragma unroll
            for (int kt = 0; kt < 4; kt++) {
                uint32_t pa0 = pp[2 * kt][0];
                uint32_t pa1 = pp[2 * kt][1];
                uint32_t pa2 = pp[2 * kt + 1][0];
                uint32_t pa3 = pp[2 * kt + 1][1];

#pragma unroll
                for (int ntp = 0; ntp < 4; ntp++) {
                    uint32_t bf0, bf1, bf2, bf3;
                    int ch = ntp * 2 + vbit;
                    ldsm_x4t(vbuf + vrowOff[kt] + ((ch ^ vrx[kt]) << 4), bf0, bf1, bf2, bf3);
                    mma_f16(co[2 * ntp][0], co[2 * ntp][1], co[2 * ntp][2], co[2 * ntp][3],
                            pa0, pa1, pa2, pa3, bf0, bf1);
                    mma_f16(co[2 * ntp + 1][0], co[2 * ntp + 1][1], co[2 * ntp + 1][2], co[2 * ntp + 1][3],
                            pa0, pa1, pa2, pa3, bf2, bf3);
                }
            }
        }

        sbuf = (sbuf + 1 == 3) ? 0 : sbuf + 1;
    }

    const float il = 1.0f / l_lo, ih = 1.0f / l_hi;
    __half* yb = y + ((size_t)b * S_LEN + q0 + w * 16 + (lane >> 2)) * D_MODEL + h * DH + 2 * jsel;
#pragma unroll
    for (int nt = 0; nt < 8; nt++) {
        *(uint32_t*)(yb + nt * 8)                       = pack_h2(co[nt][0] * il, co[nt][1] * il);
        *(uint32_t*)(yb + nt * 8 + 8 * (size_t)D_MODEL) = pack_h2(co[nt][2] * ih, co[nt][3] * ih);
    }
}

// ---------------------------------------------------------------------------
extern "C" void kernel_launch(void* const* d_in, const int* in_sizes, int n_in,
                              void* d_out, int out_size) {
    const float* x      = (const float*)d_in[0];
    const float* w_attn = (const float*)d_in[1];
    const float* w_proj = (const float*)d_in[2];
    float* out = (float*)d_out;

    __half *qkv, *yb, *xc, *wac, *wpc;
    cudaGetSymbolAddress((void**)&qkv, g_qkv);
    cudaGetSymbolAddress((void**)&yb, g_y);
    cudaGetSymbolAddress((void**)&xc, g_xc);
    cudaGetSymbolAddress((void**)&wac, g_wac);
    cudaGetSymbolAddress((void**)&wpc, g_wpc);

    cudaFuncSetAttribute(gemm_f16<true>,  cudaFuncAttributeMaxDynamicSharedMemorySize, GEMM_SMEM);
    cudaFuncSetAttribute(gemm_f16<false>, cudaFuncAttributeMaxDynamicSharedMemorySize, GEMM_SMEM);
    cudaFuncSetAttribute(attn_f16, cudaFuncAttributeMaxDynamicSharedMemorySize, ATT_SMEM);

    round_all<<<(RND_TOTAL + 255) / 256, 256>>>(x, w_attn, w_proj);

    dim3 g1(D3 / TBN, M_ROWS / TBM);
    gemm_f16<true><<<g1, 256, GEMM_SMEM>>>(xc, wac, qkv, M_ROWS, D3, D_MODEL);

    dim3 ga(S_LEN / 128, N_HEADS, BATCH);
    attn_f16<<<ga, 256, ATT_SMEM>>>(qkv, yb);

    dim3 g2(D_MODEL / TBN, M_ROWS / TBM);
    gemm_f16<false><<<g2, 256, GEMM_SMEM>>>(yb, wpc, out, M_ROWS, D_MODEL, D_MODEL);
}